// round 1
// baseline (speedup 1.0000x reference)
#include <cuda_runtime.h>
#include <math.h>

#define N_INT 20000
#define N_B   800
#define HID   512
#define NV    (N_INT + N_B)          // 20800 value rows (interior + boundary)
#define M_ROWS (NV + 3*N_INT)        // 80800 total stacked rows
#define ALPHA 0.01f

// Scratch (static device arrays; no allocation at runtime)
__device__ float g_A[M_ROWS * HID];   // activations / jet streams
__device__ float g_V[M_ROWS * HID];   // pre-activation GEMM output
__device__ float g_partial_i[2500];
__device__ float g_partial_b[100];

// ---------------------------------------------------------------------------
// Layer 0: x (2 dims) -> 512, plus jet initialization.
// Row layout of g_A:
//   [0, N_INT)              : y  (interior value)
//   [N_INT, NV)             : y  (boundary value)
//   [NV, NV+N_INT)          : d0 (d/dx stream)
//   [NV+N_INT, NV+2N)       : d1 (d/dy stream)
//   [NV+2N, NV+3N)          : S  (summed 2nd-derivative stream)
// ---------------------------------------------------------------------------
__global__ void k_layer0(const float* __restrict__ xi, const float* __restrict__ xb,
                         const float* __restrict__ W0, const float* __restrict__ b0)
{
    int t = blockIdx.x * blockDim.x + threadIdx.x;
    if (t >= NV * HID) return;
    int p = t / HID;
    int j = t - p * HID;

    float w0 = W0[j];          // W0[0][j]
    float w1 = W0[HID + j];    // W0[1][j]
    float x0, x1;
    if (p < N_INT) { x0 = xi[2*p];             x1 = xi[2*p+1]; }
    else           { int q = p - N_INT; x0 = xb[2*q]; x1 = xb[2*q+1]; }

    float v = fmaf(x0, w0, fmaf(x1, w1, b0[j]));
    float y = tanhf(v);
    g_A[p*HID + j] = y;

    if (p < N_INT) {
        float s = 1.0f - y*y;
        g_A[(NV            + p)*HID + j] = s * w0;
        g_A[(NV +   N_INT  + p)*HID + j] = s * w1;
        g_A[(NV + 2*N_INT  + p)*HID + j] = -2.0f * y * s * (w0*w0 + w1*w1);
    }
}

// ---------------------------------------------------------------------------
// SGEMM: g_V[M_ROWS x 512] = g_A[M_ROWS x 512] @ W[512 x 512]
// 128x128 tile, BK=8, 256 threads, 8x8 per thread.
// ---------------------------------------------------------------------------
__global__ __launch_bounds__(256, 2)
void k_gemm(const float* __restrict__ B)
{
    const int BM = 128, BN = 128, BK = 8;
    __shared__ float As[BK][BM];
    __shared__ float Bs[BK][BN];

    int bx = blockIdx.x;           // N tile: 0..3
    int by = blockIdx.y;           // M tile
    int tid = threadIdx.x;
    int row0 = by * BM;
    int col0 = bx * BN;

    // A-tile load mapping: thread -> (row tid/2, 4 floats at (tid%2)*4)
    int a_r = tid >> 1;
    int a_c = (tid & 1) * 4;
    // B-tile load: thread -> (row tid/32, 4 floats at (tid%32)*4)
    int b_r = tid >> 5;
    int b_c = (tid & 31) * 4;

    int tx = (tid & 15) * 8;       // output col offset in tile
    int ty = (tid >> 4) * 8;       // output row offset in tile

    float acc[8][8];
    #pragma unroll
    for (int i = 0; i < 8; i++)
        #pragma unroll
        for (int jj = 0; jj < 8; jj++) acc[i][jj] = 0.0f;

    for (int k0 = 0; k0 < HID; k0 += BK) {
        int gr = row0 + a_r;
        float4 av = make_float4(0.f, 0.f, 0.f, 0.f);
        if (gr < M_ROWS) av = *(const float4*)&g_A[gr*HID + k0 + a_c];
        As[a_c+0][a_r] = av.x; As[a_c+1][a_r] = av.y;
        As[a_c+2][a_r] = av.z; As[a_c+3][a_r] = av.w;

        float4 bv = *(const float4*)&B[(k0 + b_r)*HID + col0 + b_c];
        *(float4*)&Bs[b_r][b_c] = bv;
        __syncthreads();

        #pragma unroll
        for (int k = 0; k < BK; k++) {
            float ar[8], br[8];
            #pragma unroll
            for (int i = 0; i < 8; i++) ar[i] = As[k][ty + i];
            #pragma unroll
            for (int i = 0; i < 8; i++) br[i] = Bs[k][tx + i];
            #pragma unroll
            for (int i = 0; i < 8; i++)
                #pragma unroll
                for (int jj = 0; jj < 8; jj++)
                    acc[i][jj] = fmaf(ar[i], br[jj], acc[i][jj]);
        }
        __syncthreads();
    }

    #pragma unroll
    for (int i = 0; i < 8; i++) {
        int gr = row0 + ty + i;
        if (gr < M_ROWS) {
            #pragma unroll
            for (int jj = 0; jj < 8; jj += 4) {
                *(float4*)&g_V[gr*HID + col0 + tx + jj] =
                    make_float4(acc[i][jj], acc[i][jj+1], acc[i][jj+2], acc[i][jj+3]);
            }
        }
    }
}

// ---------------------------------------------------------------------------
// tanh-jet elementwise: g_A = jet(g_V + bias)
//   y = tanh(v+b); d' = s*p; S' = s*q - 2ys*(p0^2+p1^2)
// ---------------------------------------------------------------------------
__global__ void k_jet(const float* __restrict__ b)
{
    int t = blockIdx.x * blockDim.x + threadIdx.x;
    if (t >= NV * HID) return;
    int p = t / HID;
    int j = t - p * HID;

    float v = g_V[p*HID + j] + b[j];
    float y = tanhf(v);
    g_A[p*HID + j] = y;

    if (p < N_INT) {
        float s  = 1.0f - y*y;
        float p0 = g_V[(NV           + p)*HID + j];
        float p1 = g_V[(NV +  N_INT  + p)*HID + j];
        float q  = g_V[(NV + 2*N_INT + p)*HID + j];
        g_A[(NV           + p)*HID + j] = s * p0;
        g_A[(NV +  N_INT  + p)*HID + j] = s * p1;
        g_A[(NV + 2*N_INT + p)*HID + j] = s * q - 2.0f * y * s * (p0*p0 + p1*p1);
    }
}

// ---------------------------------------------------------------------------
// Interior loss partials: lap[p] = S2[p,:] @ W3 ; r = lap - forcing ; sum r^2
// One warp per point, 8 points per block, 2500 blocks (deterministic).
// ---------------------------------------------------------------------------
__global__ void k_final_interior(const float* __restrict__ xi, const float* __restrict__ W3)
{
    int warp = threadIdx.x >> 5;
    int lane = threadIdx.x & 31;
    int p = blockIdx.x * 8 + warp;

    float val = 0.0f;
    if (p < N_INT) {
        const float* row = &g_A[(NV + 2*N_INT + p) * HID];
        float acc = 0.0f;
        #pragma unroll 4
        for (int j = lane; j < HID; j += 32) acc = fmaf(row[j], W3[j], acc);
        #pragma unroll
        for (int o = 16; o; o >>= 1) acc += __shfl_xor_sync(0xFFFFFFFFu, acc, o);
        if (lane == 0) {
            const float PI = 3.14159265358979323846f;
            float xx = xi[2*p], yy = xi[2*p+1];
            float sy2 = sinf(PI*yy*yy), cy2 = cosf(PI*yy*yy), sx = sinf(PI*xx);
            float f = -PI*PI*(1.0f + 4.0f*yy*yy)*sx*sy2 + 2.0f*PI*sx*cy2;
            float r = acc - f;
            val = r * r;
        }
    }
    __shared__ float sh[8];
    if (lane == 0) sh[warp] = val;
    __syncthreads();
    if (threadIdx.x == 0) {
        float s = 0.0f;
        #pragma unroll
        for (int i = 0; i < 8; i++) s += sh[i];
        g_partial_i[blockIdx.x] = s;
    }
}

// ---------------------------------------------------------------------------
// Boundary loss partials: u[p] = y2_b[p,:] @ W3 + b3 ; sum u^2
// ---------------------------------------------------------------------------
__global__ void k_final_boundary(const float* __restrict__ W3, const float* __restrict__ b3)
{
    int warp = threadIdx.x >> 5;
    int lane = threadIdx.x & 31;
    int p = blockIdx.x * 8 + warp;

    float val = 0.0f;
    if (p < N_B) {
        const float* row = &g_A[(N_INT + p) * HID];
        float acc = 0.0f;
        #pragma unroll 4
        for (int j = lane; j < HID; j += 32) acc = fmaf(row[j], W3[j], acc);
        #pragma unroll
        for (int o = 16; o; o >>= 1) acc += __shfl_xor_sync(0xFFFFFFFFu, acc, o);
        if (lane == 0) {
            float u = acc + b3[0];
            val = u * u;
        }
    }
    __shared__ float sh[8];
    if (lane == 0) sh[warp] = val;
    __syncthreads();
    if (threadIdx.x == 0) {
        float s = 0.0f;
        #pragma unroll
        for (int i = 0; i < 8; i++) s += sh[i];
        g_partial_b[blockIdx.x] = s;
    }
}

// ---------------------------------------------------------------------------
// Deterministic combine: fixed-shape tree reductions, writes 3 outputs.
// ---------------------------------------------------------------------------
__global__ void k_combine(float* __restrict__ out)
{
    __shared__ float sh[256];
    int t = threadIdx.x;

    float si = 0.0f;
    for (int i = t; i < 2500; i += 256) si += g_partial_i[i];
    sh[t] = si;
    __syncthreads();
    for (int o = 128; o; o >>= 1) { if (t < o) sh[t] += sh[t + o]; __syncthreads(); }
    float interior_sum = sh[0];
    __syncthreads();

    float sb = 0.0f;
    for (int i = t; i < 100; i += 256) sb += g_partial_b[i];
    sh[t] = sb;
    __syncthreads();
    for (int o = 128; o; o >>= 1) { if (t < o) sh[t] += sh[t + o]; __syncthreads(); }

    if (t == 0) {
        float interior_loss = interior_sum / (float)N_INT;
        float boundary_loss = sh[0] / (float)N_B;
        out[0] = ALPHA * interior_loss + boundary_loss;
        out[1] = interior_loss;
        out[2] = boundary_loss;
    }
}

// ---------------------------------------------------------------------------
extern "C" void kernel_launch(void* const* d_in, const int* in_sizes, int n_in,
                              void* d_out, int out_size)
{
    const float* xi = (const float*)d_in[0];  // x_interior [20000,2]
    const float* xb = (const float*)d_in[1];  // x_boundary [800,2]
    const float* W0 = (const float*)d_in[2];  // [2,512]
    const float* b0 = (const float*)d_in[3];  // [512]
    const float* W1 = (const float*)d_in[4];  // [512,512]
    const float* b1 = (const float*)d_in[5];  // [512]
    const float* W2 = (const float*)d_in[6];  // [512,512]
    const float* b2 = (const float*)d_in[7];  // [512]
    const float* W3 = (const float*)d_in[8];  // [512,1]
    const float* b3 = (const float*)d_in[9];  // [1]

    int ew_threads = NV * HID;
    int ew_blocks  = (ew_threads + 255) / 256;
    dim3 gemm_grid(HID / 128, (M_ROWS + 127) / 128);

    k_layer0<<<ew_blocks, 256>>>(xi, xb, W0, b0);
    k_gemm<<<gemm_grid, 256>>>(W1);
    k_jet<<<ew_blocks, 256>>>(b1);
    k_gemm<<<gemm_grid, 256>>>(W2);
    k_jet<<<ew_blocks, 256>>>(b2);
    k_final_interior<<<(N_INT + 7) / 8, 256>>>(xi, W3);
    k_final_boundary<<<(N_B + 7) / 8, 256>>>(W3, b3);
    k_combine<<<1, 256>>>((float*)d_out);
}

// round 5
// speedup vs baseline: 1.0136x; 1.0136x over previous
#include <cuda_runtime.h>
#include <math.h>

#define N_INT 20000
#define N_B   800
#define HID   512
#define BROW  (4*N_INT)              // 80000: boundary rows start here
#define M_ROWS (BROW + N_B)          // 80800 total rows
#define M_TILES 632                  // ceil(80800/128)
#define INT_TILES 625                // 80000/128 : tiles 0..624 are pure interior
#define ALPHA 0.01f

// Interleaved layout: interior point p -> rows 4p+{0:y,1:d0,2:d1,3:S};
// boundary point q -> row BROW+q (value only).
// Ping-pong: layer0 -> g_A ; GEMM<1> reads g_A writes g_A2 ;
// GEMM<2> reads g_A2 writes g_S / g_Yb. Buffers selected INSIDE device code
// (never pass __device__ symbols as kernel args from host: on GB300 ATS the
// host-shadow address silently dereferences to zeros).
__device__ float g_A [M_ROWS * HID];
__device__ float g_A2[M_ROWS * HID];
__device__ float g_S [N_INT * HID];
__device__ float g_Yb[N_B * HID];
__device__ float g_partial_i[2500];
__device__ float g_partial_b[100];

// ---------------------------------------------------------------------------
// Layer 0: x -> 512 with jet init, interleaved layout.
// ---------------------------------------------------------------------------
__global__ void k_layer0(const float* __restrict__ xi, const float* __restrict__ xb,
                         const float* __restrict__ W0, const float* __restrict__ b0)
{
    int t = blockIdx.x * blockDim.x + threadIdx.x;
    if (t >= (N_INT + N_B) * HID) return;
    int p = t / HID;
    int j = t - p * HID;

    float w0 = W0[j];
    float w1 = W0[HID + j];

    if (p < N_INT) {
        float x0 = xi[2*p], x1 = xi[2*p+1];
        float v = fmaf(x0, w0, fmaf(x1, w1, b0[j]));
        float y = tanhf(v);
        float s = 1.0f - y*y;
        g_A[(size_t)(4*p + 0)*HID + j] = y;
        g_A[(size_t)(4*p + 1)*HID + j] = s * w0;
        g_A[(size_t)(4*p + 2)*HID + j] = s * w1;
        g_A[(size_t)(4*p + 3)*HID + j] = -2.0f * y * s * (w0*w0 + w1*w1);
    } else {
        int q = p - N_INT;
        float x0 = xb[2*q], x1 = xb[2*q+1];
        float v = fmaf(x0, w0, fmaf(x1, w1, b0[j]));
        g_A[(size_t)(BROW + q)*HID + j] = tanhf(v);
    }
}

// ---------------------------------------------------------------------------
// Fused SGEMM + bias + tanh-jet epilogue.
// MODE 1: out = jet(g_A @ W + b)  -> full interleaved write to g_A2
// MODE 2: out = jet(g_A2 @ W + b) -> only S rows to g_S, boundary rows to g_Yb
// Double-buffered smem, BM=BN=128, BK=8, 256 threads, 8x8 acc/thread.
// ---------------------------------------------------------------------------
template<int MODE>
__global__ __launch_bounds__(256, 2)
void k_gemm(const float* __restrict__ B, const float* __restrict__ bias)
{
    const float* __restrict__ Ain = (MODE == 1) ? g_A : g_A2;

    __shared__ float As[2][8][128];
    __shared__ float Bs[2][8][128];

    const int tid = threadIdx.x;
    const int bx  = blockIdx.x;          // 0..3 (column tile)
    const int by  = blockIdx.y;          // 0..631 (row tile)
    const int row0 = by * 128;
    const int col0 = bx * 128;

    const int a_r = tid >> 1;            // 0..127
    const int a_c = (tid & 1) * 4;       // 0 or 4
    const int b_r = tid >> 5;            // 0..7
    const int b_c = (tid & 31) * 4;      // 0..124

    const int tx = (tid & 15) * 8;
    const int ty = (tid >> 4) * 8;

    const int gr_a = row0 + a_r;
    const bool a_ok = (gr_a < M_ROWS);
    const float* a_ptr = &Ain[(size_t)gr_a * HID + a_c];
    const float* b_ptr = &B[(size_t)b_r * HID + col0 + b_c];

    float acc[8][8];
    #pragma unroll
    for (int i = 0; i < 8; i++)
        #pragma unroll
        for (int jj = 0; jj < 8; jj++) acc[i][jj] = 0.0f;

    // stage 0 preload
    {
        float4 av = make_float4(0.f,0.f,0.f,0.f);
        if (a_ok) av = *(const float4*)a_ptr;
        As[0][a_c+0][a_r] = av.x; As[0][a_c+1][a_r] = av.y;
        As[0][a_c+2][a_r] = av.z; As[0][a_c+3][a_r] = av.w;
        *(float4*)&Bs[0][b_r][b_c] = *(const float4*)b_ptr;
    }
    __syncthreads();

    int buf = 0;
    for (int k0 = 0; k0 < HID; k0 += 8) {
        const bool has_next = (k0 + 8) < HID;
        float4 nav = make_float4(0.f,0.f,0.f,0.f), nbv;
        if (has_next) {
            if (a_ok) nav = *(const float4*)(a_ptr + k0 + 8);
            nbv = *(const float4*)(b_ptr + (size_t)(k0 + 8) * HID);
        }

        #pragma unroll
        for (int k = 0; k < 8; k++) {
            float ar[8], br[8];
            *(float4*)&ar[0] = *(float4*)&As[buf][k][ty];
            *(float4*)&ar[4] = *(float4*)&As[buf][k][ty+4];
            *(float4*)&br[0] = *(float4*)&Bs[buf][k][tx];
            *(float4*)&br[4] = *(float4*)&Bs[buf][k][tx+4];
            #pragma unroll
            for (int i = 0; i < 8; i++)
                #pragma unroll
                for (int jj = 0; jj < 8; jj++)
                    acc[i][jj] = fmaf(ar[i], br[jj], acc[i][jj]);
        }

        if (has_next) {
            int nb = buf ^ 1;
            As[nb][a_c+0][a_r] = nav.x; As[nb][a_c+1][a_r] = nav.y;
            As[nb][a_c+2][a_r] = nav.z; As[nb][a_c+3][a_r] = nav.w;
            *(float4*)&Bs[nb][b_r][b_c] = nbv;
            __syncthreads();
            buf = nb;
        }
    }

    // ---- epilogue: bias + tanh-jet ----
    float bv[8];
    #pragma unroll
    for (int cc = 0; cc < 8; cc++) bv[cc] = bias[col0 + tx + cc];

    if (by < INT_TILES) {
        // pure interior tile: 8 acc rows = 2 complete jet groups
        const int q0 = (row0 + ty) >> 2;
        #pragma unroll
        for (int g = 0; g < 2; g++) {
            #pragma unroll
            for (int cc = 0; cc < 8; cc++) {
                float v  = acc[4*g+0][cc] + bv[cc];
                float y  = tanhf(v);
                float s  = 1.0f - y*y;
                float p0 = acc[4*g+1][cc];
                float p1 = acc[4*g+2][cc];
                float qq = acc[4*g+3][cc];
                acc[4*g+0][cc] = y;
                acc[4*g+1][cc] = s * p0;
                acc[4*g+2][cc] = s * p1;
                acc[4*g+3][cc] = s * qq - 2.0f * y * s * (p0*p0 + p1*p1);
            }
        }
        if (MODE == 1) {
            #pragma unroll
            for (int i = 0; i < 8; i++) {
                float* dst = &g_A2[(size_t)(row0 + ty + i) * HID + col0 + tx];
                *(float4*)dst       = make_float4(acc[i][0], acc[i][1], acc[i][2], acc[i][3]);
                *(float4*)(dst + 4) = make_float4(acc[i][4], acc[i][5], acc[i][6], acc[i][7]);
            }
        } else {
            #pragma unroll
            for (int g = 0; g < 2; g++) {
                float* dst = &g_S[(size_t)(q0 + g) * HID + col0 + tx];
                *(float4*)dst       = make_float4(acc[4*g+3][0], acc[4*g+3][1], acc[4*g+3][2], acc[4*g+3][3]);
                *(float4*)(dst + 4) = make_float4(acc[4*g+3][4], acc[4*g+3][5], acc[4*g+3][6], acc[4*g+3][7]);
            }
        }
    } else {
        // boundary tile: plain tanh
        #pragma unroll
        for (int i = 0; i < 8; i++) {
            int gr = row0 + ty + i;
            if (gr < M_ROWS) {
                float o[8];
                #pragma unroll
                for (int cc = 0; cc < 8; cc++) o[cc] = tanhf(acc[i][cc] + bv[cc]);
                float* dst = (MODE == 1)
                    ? &g_A2[(size_t)gr * HID + col0 + tx]
                    : &g_Yb[(size_t)(gr - BROW) * HID + col0 + tx];
                *(float4*)dst       = make_float4(o[0], o[1], o[2], o[3]);
                *(float4*)(dst + 4) = make_float4(o[4], o[5], o[6], o[7]);
            }
        }
    }
}

// ---------------------------------------------------------------------------
// Interior loss partials: lap[p] = g_S[p,:] @ W3 ; r = lap - f ; sum r^2
// ---------------------------------------------------------------------------
__global__ void k_final_interior(const float* __restrict__ xi, const float* __restrict__ W3)
{
    int warp = threadIdx.x >> 5;
    int lane = threadIdx.x & 31;
    int p = blockIdx.x * 8 + warp;

    float val = 0.0f;
    if (p < N_INT) {
        const float* row = &g_S[(size_t)p * HID];
        float acc = 0.0f;
        #pragma unroll 4
        for (int j = lane; j < HID; j += 32) acc = fmaf(row[j], W3[j], acc);
        #pragma unroll
        for (int o = 16; o; o >>= 1) acc += __shfl_xor_sync(0xFFFFFFFFu, acc, o);
        if (lane == 0) {
            const float PI = 3.14159265358979323846f;
            float xx = xi[2*p], yy = xi[2*p+1];
            float sy2 = sinf(PI*yy*yy), cy2 = cosf(PI*yy*yy), sx = sinf(PI*xx);
            float f = -PI*PI*(1.0f + 4.0f*yy*yy)*sx*sy2 + 2.0f*PI*sx*cy2;
            float r = acc - f;
            val = r * r;
        }
    }
    __shared__ float sh[8];
    if (lane == 0) sh[warp] = val;
    __syncthreads();
    if (threadIdx.x == 0) {
        float s = 0.0f;
        #pragma unroll
        for (int i = 0; i < 8; i++) s += sh[i];
        g_partial_i[blockIdx.x] = s;
    }
}

__global__ void k_final_boundary(const float* __restrict__ W3, const float* __restrict__ b3)
{
    int warp = threadIdx.x >> 5;
    int lane = threadIdx.x & 31;
    int p = blockIdx.x * 8 + warp;

    float val = 0.0f;
    if (p < N_B) {
        const float* row = &g_Yb[(size_t)p * HID];
        float acc = 0.0f;
        #pragma unroll 4
        for (int j = lane; j < HID; j += 32) acc = fmaf(row[j], W3[j], acc);
        #pragma unroll
        for (int o = 16; o; o >>= 1) acc += __shfl_xor_sync(0xFFFFFFFFu, acc, o);
        if (lane == 0) {
            float u = acc + b3[0];
            val = u * u;
        }
    }
    __shared__ float sh[8];
    if (lane == 0) sh[warp] = val;
    __syncthreads();
    if (threadIdx.x == 0) {
        float s = 0.0f;
        #pragma unroll
        for (int i = 0; i < 8; i++) s += sh[i];
        g_partial_b[blockIdx.x] = s;
    }
}

__global__ void k_combine(float* __restrict__ out)
{
    __shared__ float sh[256];
    int t = threadIdx.x;

    float si = 0.0f;
    for (int i = t; i < 2500; i += 256) si += g_partial_i[i];
    sh[t] = si;
    __syncthreads();
    for (int o = 128; o; o >>= 1) { if (t < o) sh[t] += sh[t + o]; __syncthreads(); }
    float interior_sum = sh[0];
    __syncthreads();

    float sb = 0.0f;
    for (int i = t; i < 100; i += 256) sb += g_partial_b[i];
    sh[t] = sb;
    __syncthreads();
    for (int o = 128; o; o >>= 1) { if (t < o) sh[t] += sh[t + o]; __syncthreads(); }

    if (t == 0) {
        float interior_loss = interior_sum / (float)N_INT;
        float boundary_loss = sh[0] / (float)N_B;
        out[0] = ALPHA * interior_loss + boundary_loss;
        out[1] = interior_loss;
        out[2] = boundary_loss;
    }
}

// ---------------------------------------------------------------------------
extern "C" void kernel_launch(void* const* d_in, const int* in_sizes, int n_in,
                              void* d_out, int out_size)
{
    const float* xi = (const float*)d_in[0];
    const float* xb = (const float*)d_in[1];
    const float* W0 = (const float*)d_in[2];
    const float* b0 = (const float*)d_in[3];
    const float* W1 = (const float*)d_in[4];
    const float* b1 = (const float*)d_in[5];
    const float* W2 = (const float*)d_in[6];
    const float* b2 = (const float*)d_in[7];
    const float* W3 = (const float*)d_in[8];
    const float* b3 = (const float*)d_in[9];

    int ew_threads = (N_INT + N_B) * HID;
    int ew_blocks  = (ew_threads + 255) / 256;
    dim3 gemm_grid(HID / 128, M_TILES);

    k_layer0<<<ew_blocks, 256>>>(xi, xb, W0, b0);
    k_gemm<1><<<gemm_grid, 256>>>(W1, b1);
    k_gemm<2><<<gemm_grid, 256>>>(W2, b2);
    k_final_interior<<<(N_INT + 7) / 8, 256>>>(xi, W3);
    k_final_boundary<<<(N_B + 7) / 8, 256>>>(W3, b3);
    k_combine<<<1, 256>>>((float*)d_out);
}

// round 7
// speedup vs baseline: 1.8242x; 1.7997x over previous
#include <cuda_runtime.h>
#include <cuda_fp16.h>
#include <math.h>
#include <stdint.h>

#define N_INT 20000
#define N_B   800
#define HID   512
#define BROW  (4*N_INT)              // 80000
#define M_ROWS (BROW + N_B)          // 80800
#define M_TILES 632
#define INT_TILES 625
#define M_PAD (M_TILES*128)          // 80896 (pad rows stay zero forever)
#define ALPHA 0.01f
#define NCH 16                       // 512/32 k-chunks

// smem: per stage: Ahi/Alo/Bhi/Blo, each 128 rows x 40 halves (pad for ldmatrix)
#define SROW 40
#define SM_AHI 0
#define SM_ALO 10240
#define SM_BHI 20480
#define SM_BLO 30720
#define STAGE  40960
#define SMEM_DYN (2*STAGE)

// Activations as hi/lo fp16 pairs (Markidis split). Ping-pong A -> A2.
__device__ __half g_Ahi [(size_t)M_PAD * HID];
__device__ __half g_Alo [(size_t)M_PAD * HID];
__device__ __half g_A2hi[(size_t)M_PAD * HID];
__device__ __half g_A2lo[(size_t)M_PAD * HID];
__device__ __half g_W1hi[HID * HID];   // [n][k]
__device__ __half g_W1lo[HID * HID];
__device__ __half g_W2hi[HID * HID];
__device__ __half g_W2lo[HID * HID];
__device__ float  g_S [(size_t)N_INT * HID];
__device__ float  g_Yb[(size_t)N_B * HID];
__device__ float  g_partial_i[2500];
__device__ float  g_partial_b[100];

// ------------------------------- helpers -----------------------------------
static __device__ __forceinline__ uint32_t smem_u32(const void* p) {
    uint32_t a;
    asm("{ .reg .u64 t; cvta.to.shared.u64 t, %1; cvt.u32.u64 %0, t; }" : "=r"(a) : "l"(p));
    return a;
}
static __device__ __forceinline__ void cp16(uint32_t dst, const void* src) {
    asm volatile("cp.async.cg.shared.global [%0], [%1], 16;" :: "r"(dst), "l"(src));
}
static __device__ __forceinline__ void ldsm4(uint32_t* r, uint32_t addr) {
    asm volatile("ldmatrix.sync.aligned.m8n8.x4.shared.b16 {%0,%1,%2,%3}, [%4];"
                 : "=r"(r[0]), "=r"(r[1]), "=r"(r[2]), "=r"(r[3]) : "r"(addr));
}
static __device__ __forceinline__ void mma16816(float* d, const uint32_t* a, const uint32_t* b) {
    asm volatile(
        "mma.sync.aligned.m16n8k16.row.col.f32.f16.f16.f32 "
        "{%0,%1,%2,%3}, {%4,%5,%6,%7}, {%8,%9}, {%0,%1,%2,%3};"
        : "+f"(d[0]), "+f"(d[1]), "+f"(d[2]), "+f"(d[3])
        : "r"(a[0]), "r"(a[1]), "r"(a[2]), "r"(a[3]), "r"(b[0]), "r"(b[1]));
}
static __device__ __forceinline__ void hsplit(float x, uint32_t& h, uint32_t& l) {
    __half hh = __float2half_rn(x);
    float  r  = x - __half2float(hh);
    __half ll = __float2half_rn(r);
    h = __half_as_ushort(hh);
    l = __half_as_ushort(ll);
}

// ---------------------------------------------------------------------------
// Layer 0: x -> 512 with jet init, interleaved hi/lo fp16 output.
// block = point p (0..20799), 256 threads = 2 cols each.
// ---------------------------------------------------------------------------
__global__ void k_layer0(const float* __restrict__ xi, const float* __restrict__ xb,
                         const float* __restrict__ W0, const float* __restrict__ b0)
{
    const int p = blockIdx.x;
    const int j = threadIdx.x * 2;

    float w0a = W0[j],       w0b = W0[j+1];
    float w1a = W0[HID + j], w1b = W0[HID + j + 1];
    float b0a = b0[j],       b0b = b0[j+1];

    if (p < N_INT) {
        float x0 = xi[2*p], x1 = xi[2*p+1];
        float va = fmaf(x0, w0a, fmaf(x1, w1a, b0a));
        float vb = fmaf(x0, w0b, fmaf(x1, w1b, b0b));
        float ya = tanhf(va), yb = tanhf(vb);
        float sa = 1.0f - ya*ya, sb = 1.0f - yb*yb;
        float vals[4][2] = {
            { ya, yb },
            { sa * w0a, sb * w0b },
            { sa * w1a, sb * w1b },
            { -2.0f*ya*sa*(w0a*w0a + w1a*w1a), -2.0f*yb*sb*(w0b*w0b + w1b*w1b) }
        };
        #pragma unroll
        for (int t = 0; t < 4; t++) {
            uint32_t h0, l0, h1, l1;
            hsplit(vals[t][0], h0, l0);
            hsplit(vals[t][1], h1, l1);
            size_t off = (size_t)(4*p + t) * HID + j;
            *(uint32_t*)&g_Ahi[off] = h0 | (h1 << 16);
            *(uint32_t*)&g_Alo[off] = l0 | (l1 << 16);
        }
    } else {
        int q = p - N_INT;
        float x0 = xb[2*q], x1 = xb[2*q+1];
        float va = fmaf(x0, w0a, fmaf(x1, w1a, b0a));
        float vb = fmaf(x0, w0b, fmaf(x1, w1b, b0b));
        float ya = tanhf(va), yb = tanhf(vb);
        uint32_t h0, l0, h1, l1;
        hsplit(ya, h0, l0);
        hsplit(yb, h1, l1);
        size_t off = (size_t)(BROW + q) * HID + j;
        *(uint32_t*)&g_Ahi[off] = h0 | (h1 << 16);
        *(uint32_t*)&g_Alo[off] = l0 | (l1 << 16);
    }
}

// ---------------------------------------------------------------------------
// Weight transpose + fp16 split: Wt*[n][k] = split(W[k][n])
// ---------------------------------------------------------------------------
template<int WHICH>
__global__ void k_transpose(const float* __restrict__ W)
{
    __half* __restrict__ Whi = (WHICH == 1) ? g_W1hi : g_W2hi;
    __half* __restrict__ Wlo = (WHICH == 1) ? g_W1lo : g_W2lo;
    __shared__ float ts[32][33];
    int n0 = blockIdx.x * 32, k0 = blockIdx.y * 32;
    ts[threadIdx.y][threadIdx.x] = W[(size_t)(k0 + threadIdx.y) * HID + n0 + threadIdx.x];
    __syncthreads();
    float v = ts[threadIdx.x][threadIdx.y];   // = W[k0+tx][n0+ty]
    uint32_t h, l;
    hsplit(v, h, l);
    size_t off = (size_t)(n0 + threadIdx.y) * HID + k0 + threadIdx.x;
    Whi[off] = __ushort_as_half((unsigned short)h);
    Wlo[off] = __ushort_as_half((unsigned short)l);
}

// ---------------------------------------------------------------------------
// fp16 3-split GEMM via mma.sync + fused bias/tanh-jet epilogue.
// MODE 1: jet(A @ W1 + b1) -> g_A2hi/lo (full interleaved)
// MODE 2: jet(A2 @ W2 + b2) -> S rows (fp32) to g_S, boundary rows to g_Yb
// BM=128, BN=128, BK=32, 256 thr (8 warps, 64x32 warp tiles), cp.async x2.
// ---------------------------------------------------------------------------
template<int MODE>
__global__ __launch_bounds__(256, 1)
void k_mma(const float* __restrict__ bias)
{
    const __half* __restrict__ Ahi = (MODE == 1) ? g_Ahi : g_A2hi;
    const __half* __restrict__ Alo = (MODE == 1) ? g_Alo : g_A2lo;
    const __half* __restrict__ Whi = (MODE == 1) ? g_W1hi : g_W2hi;
    const __half* __restrict__ Wlo = (MODE == 1) ? g_W1lo : g_W2lo;

    extern __shared__ char smem[];
    const uint32_t sbase = smem_u32(smem);

    const int tid  = threadIdx.x;
    const int lane = tid & 31;
    const int wid  = tid >> 5;
    const int wm   = wid >> 2;        // 0..1
    const int wn   = wid & 3;         // 0..3
    const int row0 = blockIdx.y * 128;
    const int col0 = blockIdx.x * 128;

    // ldmatrix lane offsets (in halves)
    const int grp = lane >> 3, idx = lane & 7;
    const int aoff = ((grp & 1) * 8 + idx) * SROW + (grp >> 1) * 8;
    const int boff = ((grp >> 1) * 8 + idx) * SROW + (grp & 1) * 8;

    float acc[4][4][4];
    #pragma unroll
    for (int mt = 0; mt < 4; mt++)
        #pragma unroll
        for (int nt = 0; nt < 4; nt++)
            #pragma unroll
            for (int q = 0; q < 4; q++) acc[mt][nt][q] = 0.0f;

    // prefetch lambda: chunk c -> stage base (u32 smem addr)
    const int fr = tid >> 1;            // 0..127
    const int fs = (tid & 1) * 16;      // 0 or 16 halves
    auto prefetch = [&](int c, uint32_t st) {
        size_t ga = (size_t)(row0 + fr) * HID + c * 32 + fs;
        size_t gb = (size_t)(col0 + fr) * HID + c * 32 + fs;
        uint32_t d = st + SM_AHI + (fr * SROW + fs) * 2;
        cp16(d, Ahi + ga);  cp16(d + 16, Ahi + ga + 8);
        d = st + SM_ALO + (fr * SROW + fs) * 2;
        cp16(d, Alo + ga);  cp16(d + 16, Alo + ga + 8);
        d = st + SM_BHI + (fr * SROW + fs) * 2;
        cp16(d, Whi + gb);  cp16(d + 16, Whi + gb + 8);
        d = st + SM_BLO + (fr * SROW + fs) * 2;
        cp16(d, Wlo + gb);  cp16(d + 16, Wlo + gb + 8);
        asm volatile("cp.async.commit_group;" ::: "memory");
    };

    prefetch(0, sbase);

    for (int c = 0; c < NCH; c++) {
        const uint32_t cur = sbase + (uint32_t)(c & 1) * STAGE;
        if (c + 1 < NCH) {
            prefetch(c + 1, sbase + (uint32_t)((c + 1) & 1) * STAGE);
            asm volatile("cp.async.wait_group 1;" ::: "memory");
        } else {
            asm volatile("cp.async.wait_group 0;" ::: "memory");
        }
        __syncthreads();

        #pragma unroll
        for (int ks = 0; ks < 2; ks++) {
            uint32_t ahi[4][4], alo[4][4], bhi[2][4], blo[2][4];
            #pragma unroll
            for (int mt = 0; mt < 4; mt++) {
                uint32_t base = cur + 2u * ((wm*64 + mt*16) * SROW + ks*16 + aoff);
                ldsm4(ahi[mt], base + SM_AHI);
                ldsm4(alo[mt], base + SM_ALO);
            }
            #pragma unroll
            for (int np = 0; np < 2; np++) {
                uint32_t base = cur + 2u * ((wn*32 + np*16) * SROW + ks*16 + boff);
                ldsm4(bhi[np], base + SM_BHI);
                ldsm4(blo[np], base + SM_BLO);
            }
            #pragma unroll
            for (int mt = 0; mt < 4; mt++)
                #pragma unroll
                for (int nt = 0; nt < 4; nt++) {
                    const uint32_t* bh = &bhi[nt >> 1][(nt & 1) * 2];
                    const uint32_t* bl = &blo[nt >> 1][(nt & 1) * 2];
                    mma16816(acc[mt][nt], ahi[mt], bh);
                    mma16816(acc[mt][nt], alo[mt], bh);
                    mma16816(acc[mt][nt], ahi[mt], bl);
                }
        }
        __syncthreads();
    }

    // ---- epilogue: bias + tanh-jet ----
    float bb[4][2];
    #pragma unroll
    for (int nt = 0; nt < 4; nt++)
        #pragma unroll
        for (int j = 0; j < 2; j++)
            bb[nt][j] = __ldg(&bias[col0 + wn*32 + nt*8 + (lane & 3)*2 + j]);

    const int role = (lane >> 2) & 3;
    const int srcL = (lane & ~15) | (lane & 3);

    if (blockIdx.y < INT_TILES) {
        #pragma unroll
        for (int mt = 0; mt < 4; mt++)
            #pragma unroll
            for (int h = 0; h < 2; h++) {
                const int grow = row0 + wm*64 + mt*16 + (lane >> 2) + 8*h;
                #pragma unroll
                for (int nt = 0; nt < 4; nt++) {
                    float o[2];
                    #pragma unroll
                    for (int j = 0; j < 2; j++) {
                        float x  = acc[mt][nt][h*2 + j];
                        float v  = __shfl_sync(0xFFFFFFFFu, x, srcL);
                        float p0 = __shfl_sync(0xFFFFFFFFu, x, srcL + 4);
                        float p1 = __shfl_sync(0xFFFFFFFFu, x, srcL + 8);
                        float y  = tanhf(v + bb[nt][j]);
                        float s  = 1.0f - y*y;
                        float r;
                        if      (role == 0) r = y;
                        else if (role == 1) r = s * p0;
                        else if (role == 2) r = s * p1;
                        else                r = fmaf(s, x, -2.0f * y * s * (p0*p0 + p1*p1));
                        o[j] = r;
                    }
                    const int colb = col0 + wn*32 + nt*8 + (lane & 3)*2;
                    if (MODE == 1) {
                        uint32_t h0, l0, h1, l1;
                        hsplit(o[0], h0, l0);
                        hsplit(o[1], h1, l1);
                        size_t off = (size_t)grow * HID + colb;
                        *(uint32_t*)&g_A2hi[off] = h0 | (h1 << 16);
                        *(uint32_t*)&g_A2lo[off] = l0 | (l1 << 16);
                    } else if (role == 3) {
                        *(float2*)&g_S[(size_t)(grow >> 2) * HID + colb] = make_float2(o[0], o[1]);
                    }
                }
            }
    } else {
        #pragma unroll
        for (int mt = 0; mt < 4; mt++)
            #pragma unroll
            for (int h = 0; h < 2; h++) {
                const int grow = row0 + wm*64 + mt*16 + (lane >> 2) + 8*h;
                if (grow < M_ROWS) {
                    #pragma unroll
                    for (int nt = 0; nt < 4; nt++) {
                        float o0 = tanhf(acc[mt][nt][h*2 + 0] + bb[nt][0]);
                        float o1 = tanhf(acc[mt][nt][h*2 + 1] + bb[nt][1]);
                        const int colb = col0 + wn*32 + nt*8 + (lane & 3)*2;
                        if (MODE == 1) {
                            uint32_t h0, l0, h1, l1;
                            hsplit(o0, h0, l0);
                            hsplit(o1, h1, l1);
                            size_t off = (size_t)grow * HID + colb;
                            *(uint32_t*)&g_A2hi[off] = h0 | (h1 << 16);
                            *(uint32_t*)&g_A2lo[off] = l0 | (l1 << 16);
                        } else {
                            *(float2*)&g_Yb[(size_t)(grow - BROW) * HID + colb] = make_float2(o0, o1);
                        }
                    }
                }
            }
    }
}

// ---------------------------------------------------------------------------
// Final reductions (unchanged, proven).
// ---------------------------------------------------------------------------
__global__ void k_final_interior(const float* __restrict__ xi, const float* __restrict__ W3)
{
    int warp = threadIdx.x >> 5;
    int lane = threadIdx.x & 31;
    int p = blockIdx.x * 8 + warp;

    float val = 0.0f;
    if (p < N_INT) {
        const float* row = &g_S[(size_t)p * HID];
        float acc = 0.0f;
        #pragma unroll 4
        for (int j = lane; j < HID; j += 32) acc = fmaf(row[j], W3[j], acc);
        #pragma unroll
        for (int o = 16; o; o >>= 1) acc += __shfl_xor_sync(0xFFFFFFFFu, acc, o);
        if (lane == 0) {
            const float PI = 3.14159265358979323846f;
            float xx = xi[2*p], yy = xi[2*p+1];
            float sy2 = sinf(PI*yy*yy), cy2 = cosf(PI*yy*yy), sx = sinf(PI*xx);
            float f = -PI*PI*(1.0f + 4.0f*yy*yy)*sx*sy2 + 2.0f*PI*sx*cy2;
            float r = acc - f;
            val = r * r;
        }
    }
    __shared__ float sh[8];
    if (lane == 0) sh[warp] = val;
    __syncthreads();
    if (threadIdx.x == 0) {
        float s = 0.0f;
        #pragma unroll
        for (int i = 0; i < 8; i++) s += sh[i];
        g_partial_i[blockIdx.x] = s;
    }
}

__global__ void k_final_boundary(const float* __restrict__ W3, const float* __restrict__ b3)
{
    int warp = threadIdx.x >> 5;
    int lane = threadIdx.x & 31;
    int p = blockIdx.x * 8 + warp;

    float val = 0.0f;
    if (p < N_B) {
        const float* row = &g_Yb[(size_t)p * HID];
        float acc = 0.0f;
        #pragma unroll 4
        for (int j = lane; j < HID; j += 32) acc = fmaf(row[j], W3[j], acc);
        #pragma unroll
        for (int o = 16; o; o >>= 1) acc += __shfl_xor_sync(0xFFFFFFFFu, acc, o);
        if (lane == 0) {
            float u = acc + b3[0];
            val = u * u;
        }
    }
    __shared__ float sh[8];
    if (lane == 0) sh[warp] = val;
    __syncthreads();
    if (threadIdx.x == 0) {
        float s = 0.0f;
        #pragma unroll
        for (int i = 0; i < 8; i++) s += sh[i];
        g_partial_b[blockIdx.x] = s;
    }
}

__global__ void k_combine(float* __restrict__ out)
{
    __shared__ float sh[256];
    int t = threadIdx.x;

    float si = 0.0f;
    for (int i = t; i < 2500; i += 256) si += g_partial_i[i];
    sh[t] = si;
    __syncthreads();
    for (int o = 128; o; o >>= 1) { if (t < o) sh[t] += sh[t + o]; __syncthreads(); }
    float interior_sum = sh[0];
    __syncthreads();

    float sb = 0.0f;
    for (int i = t; i < 100; i += 256) sb += g_partial_b[i];
    sh[t] = sb;
    __syncthreads();
    for (int o = 128; o; o >>= 1) { if (t < o) sh[t] += sh[t + o]; __syncthreads(); }

    if (t == 0) {
        float interior_loss = interior_sum / (float)N_INT;
        float boundary_loss = sh[0] / (float)N_B;
        out[0] = ALPHA * interior_loss + boundary_loss;
        out[1] = interior_loss;
        out[2] = boundary_loss;
    }
}

// ---------------------------------------------------------------------------
extern "C" void kernel_launch(void* const* d_in, const int* in_sizes, int n_in,
                              void* d_out, int out_size)
{
    const float* xi = (const float*)d_in[0];
    const float* xb = (const float*)d_in[1];
    const float* W0 = (const float*)d_in[2];
    const float* b0 = (const float*)d_in[3];
    const float* W1 = (const float*)d_in[4];
    const float* b1 = (const float*)d_in[5];
    const float* W2 = (const float*)d_in[6];
    const float* b2 = (const float*)d_in[7];
    const float* W3 = (const float*)d_in[8];
    const float* b3 = (const float*)d_in[9];

    cudaFuncSetAttribute(k_mma<1>, cudaFuncAttributeMaxDynamicSharedMemorySize, SMEM_DYN);
    cudaFuncSetAttribute(k_mma<2>, cudaFuncAttributeMaxDynamicSharedMemorySize, SMEM_DYN);

    dim3 tgrid(16, 16), tblock(32, 32);
    dim3 mma_grid(4, M_TILES);

    k_layer0<<<N_INT + N_B, 256>>>(xi, xb, W0, b0);
    k_transpose<1><<<tgrid, tblock>>>(W1);
    k_transpose<2><<<tgrid, tblock>>>(W2);
    k_mma<1><<<mma_grid, 256, SMEM_DYN>>>(b1);
    k_mma<2><<<mma_grid, 256, SMEM_DYN>>>(b2);
    k_final_interior<<<(N_INT + 7) / 8, 256>>>(xi, W3);
    k_final_boundary<<<(N_B + 7) / 8, 256>>>(W3, b3);
    k_combine<<<1, 256>>>((float*)d_out);
}

// round 8
// speedup vs baseline: 2.1486x; 1.1778x over previous
#include <cuda_runtime.h>
#include <cuda_fp16.h>
#include <math.h>
#include <stdint.h>

#define N_INT 20000
#define N_B   800
#define HID   512
#define BROW  (4*N_INT)              // 80000
#define M_ROWS (BROW + N_B)          // 80800
#define M_TILES 632
#define INT_TILES 625
#define M_PAD (M_TILES*128)          // 80896 (pad rows stay zero forever)
#define ALPHA 0.01f
#define NCH 16                       // 512/32 k-chunks

// smem: per stage: Ahi/Alo/Bhi/Blo, each 128 rows x 40 halves (pad -> ldmatrix conflict-free)
#define SROW 40
#define SM_AHI 0
#define SM_ALO 10240
#define SM_BHI 20480
#define SM_BLO 30720
#define STAGE  40960
#define SMEM_DYN (2*STAGE)

// Activations as hi/lo fp16 pairs (Markidis split). Ping-pong A -> A2.
__device__ __half g_Ahi [(size_t)M_PAD * HID];
__device__ __half g_Alo [(size_t)M_PAD * HID];
__device__ __half g_A2hi[(size_t)M_PAD * HID];
__device__ __half g_A2lo[(size_t)M_PAD * HID];
__device__ __half g_W1hi[HID * HID];   // [n][k]
__device__ __half g_W1lo[HID * HID];
__device__ __half g_W2hi[HID * HID];
__device__ __half g_W2lo[HID * HID];
__device__ float  g_S [(size_t)N_INT * HID];
__device__ float  g_Yb[(size_t)N_B * HID];
__device__ float  g_partial_i[2500];
__device__ float  g_partial_b[100];

// ------------------------------- helpers -----------------------------------
static __device__ __forceinline__ uint32_t smem_u32(const void* p) {
    uint32_t a;
    asm("{ .reg .u64 t; cvta.to.shared.u64 t, %1; cvt.u32.u64 %0, t; }" : "=r"(a) : "l"(p));
    return a;
}
static __device__ __forceinline__ void cp16(uint32_t dst, const void* src) {
    asm volatile("cp.async.cg.shared.global [%0], [%1], 16;" :: "r"(dst), "l"(src));
}
static __device__ __forceinline__ void ldsm4(uint32_t* r, uint32_t addr) {
    asm volatile("ldmatrix.sync.aligned.m8n8.x4.shared.b16 {%0,%1,%2,%3}, [%4];"
                 : "=r"(r[0]), "=r"(r[1]), "=r"(r[2]), "=r"(r[3]) : "r"(addr));
}
static __device__ __forceinline__ void mma16816(float* d, const uint32_t* a, const uint32_t* b) {
    asm volatile(
        "mma.sync.aligned.m16n8k16.row.col.f32.f16.f16.f32 "
        "{%0,%1,%2,%3}, {%4,%5,%6,%7}, {%8,%9}, {%0,%1,%2,%3};"
        : "+f"(d[0]), "+f"(d[1]), "+f"(d[2]), "+f"(d[3])
        : "r"(a[0]), "r"(a[1]), "r"(a[2]), "r"(a[3]), "r"(b[0]), "r"(b[1]));
}
static __device__ __forceinline__ void hsplit(float x, uint32_t& h, uint32_t& l) {
    __half hh = __float2half_rn(x);
    float  r  = x - __half2float(hh);
    __half ll = __float2half_rn(r);
    h = __half_as_ushort(hh);
    l = __half_as_ushort(ll);
}

// ---------------------------------------------------------------------------
// Layer 0: x -> 512 with jet init, interleaved hi/lo fp16 output.
// ---------------------------------------------------------------------------
__global__ void k_layer0(const float* __restrict__ xi, const float* __restrict__ xb,
                         const float* __restrict__ W0, const float* __restrict__ b0)
{
    const int p = blockIdx.x;
    const int j = threadIdx.x * 2;

    float w0a = W0[j],       w0b = W0[j+1];
    float w1a = W0[HID + j], w1b = W0[HID + j + 1];
    float b0a = b0[j],       b0b = b0[j+1];

    if (p < N_INT) {
        float x0 = xi[2*p], x1 = xi[2*p+1];
        float va = fmaf(x0, w0a, fmaf(x1, w1a, b0a));
        float vb = fmaf(x0, w0b, fmaf(x1, w1b, b0b));
        float ya = tanhf(va), yb = tanhf(vb);
        float sa = 1.0f - ya*ya, sb = 1.0f - yb*yb;
        float vals[4][2] = {
            { ya, yb },
            { sa * w0a, sb * w0b },
            { sa * w1a, sb * w1b },
            { -2.0f*ya*sa*(w0a*w0a + w1a*w1a), -2.0f*yb*sb*(w0b*w0b + w1b*w1b) }
        };
        #pragma unroll
        for (int t = 0; t < 4; t++) {
            uint32_t h0, l0, h1, l1;
            hsplit(vals[t][0], h0, l0);
            hsplit(vals[t][1], h1, l1);
            size_t off = (size_t)(4*p + t) * HID + j;
            *(uint32_t*)&g_Ahi[off] = h0 | (h1 << 16);
            *(uint32_t*)&g_Alo[off] = l0 | (l1 << 16);
        }
    } else {
        int q = p - N_INT;
        float x0 = xb[2*q], x1 = xb[2*q+1];
        float va = fmaf(x0, w0a, fmaf(x1, w1a, b0a));
        float vb = fmaf(x0, w0b, fmaf(x1, w1b, b0b));
        float ya = tanhf(va), yb = tanhf(vb);
        uint32_t h0, l0, h1, l1;
        hsplit(ya, h0, l0);
        hsplit(yb, h1, l1);
        size_t off = (size_t)(BROW + q) * HID + j;
        *(uint32_t*)&g_Ahi[off] = h0 | (h1 << 16);
        *(uint32_t*)&g_Alo[off] = l0 | (l1 << 16);
    }
}

// ---------------------------------------------------------------------------
// Weight transpose + fp16 split: Wt*[n][k] = split(W[k][n])
// ---------------------------------------------------------------------------
template<int WHICH>
__global__ void k_transpose(const float* __restrict__ W)
{
    __half* __restrict__ Whi = (WHICH == 1) ? g_W1hi : g_W2hi;
    __half* __restrict__ Wlo = (WHICH == 1) ? g_W1lo : g_W2lo;
    __shared__ float ts[32][33];
    int n0 = blockIdx.x * 32, k0 = blockIdx.y * 32;
    ts[threadIdx.y][threadIdx.x] = W[(size_t)(k0 + threadIdx.y) * HID + n0 + threadIdx.x];
    __syncthreads();
    float v = ts[threadIdx.x][threadIdx.y];   // = W[k0+tx][n0+ty]
    uint32_t h, l;
    hsplit(v, h, l);
    size_t off = (size_t)(n0 + threadIdx.y) * HID + k0 + threadIdx.x;
    Whi[off] = __ushort_as_half((unsigned short)h);
    Wlo[off] = __ushort_as_half((unsigned short)l);
}

// ---------------------------------------------------------------------------
// fp16 3-split GEMM via mma.sync + fused bias/tanh-jet epilogue.
// MODE 1: jet(A @ W1 + b1) -> g_A2hi/lo (full interleaved)
// MODE 2: jet(A2 @ W2 + b2) -> S rows (fp32) to g_S, boundary rows to g_Yb
// BM=128, BN=128, BK=32, 512 thr (16 warps in 4x4 grid, 32x32 warp tiles).
// ---------------------------------------------------------------------------
template<int MODE>
__global__ __launch_bounds__(512, 1)
void k_mma(const float* __restrict__ bias)
{
    const __half* __restrict__ Ahi = (MODE == 1) ? g_Ahi : g_A2hi;
    const __half* __restrict__ Alo = (MODE == 1) ? g_Alo : g_A2lo;
    const __half* __restrict__ Whi = (MODE == 1) ? g_W1hi : g_W2hi;
    const __half* __restrict__ Wlo = (MODE == 1) ? g_W1lo : g_W2lo;

    extern __shared__ char smem[];
    const uint32_t sbase = smem_u32(smem);

    const int tid  = threadIdx.x;
    const int lane = tid & 31;
    const int wid  = tid >> 5;
    const int wm   = wid >> 2;        // 0..3 : rows wm*32
    const int wn   = wid & 3;         // 0..3 : cols wn*32
    const int row0 = blockIdx.y * 128;
    const int col0 = blockIdx.x * 128;

    // ldmatrix lane offsets (in halves)
    const int grp = lane >> 3, idx = lane & 7;
    const int aoff = ((grp & 1) * 8 + idx) * SROW + (grp >> 1) * 8;
    const int boff = ((grp >> 1) * 8 + idx) * SROW + (grp & 1) * 8;

    float acc[2][4][4];
    #pragma unroll
    for (int mt = 0; mt < 2; mt++)
        #pragma unroll
        for (int nt = 0; nt < 4; nt++)
            #pragma unroll
            for (int q = 0; q < 4; q++) acc[mt][nt][q] = 0.0f;

    // prefetch: 512 threads, 1 x 16B per thread per tile
    const int fr = tid >> 2;            // 0..127
    const int fs = (tid & 3) * 8;       // 0,8,16,24 halves
    auto prefetch = [&](int c, uint32_t st) {
        size_t ga = (size_t)(row0 + fr) * HID + c * 32 + fs;
        size_t gb = (size_t)(col0 + fr) * HID + c * 32 + fs;
        uint32_t o = (uint32_t)(fr * SROW + fs) * 2;
        cp16(st + SM_AHI + o, Ahi + ga);
        cp16(st + SM_ALO + o, Alo + ga);
        cp16(st + SM_BHI + o, Whi + gb);
        cp16(st + SM_BLO + o, Wlo + gb);
        asm volatile("cp.async.commit_group;" ::: "memory");
    };

    prefetch(0, sbase);

    for (int c = 0; c < NCH; c++) {
        const uint32_t cur = sbase + (uint32_t)(c & 1) * STAGE;
        if (c + 1 < NCH) {
            prefetch(c + 1, sbase + (uint32_t)((c + 1) & 1) * STAGE);
            asm volatile("cp.async.wait_group 1;" ::: "memory");
        } else {
            asm volatile("cp.async.wait_group 0;" ::: "memory");
        }
        __syncthreads();

        #pragma unroll
        for (int ks = 0; ks < 2; ks++) {
            uint32_t ahi[2][4], alo[2][4], bhi[2][4], blo[2][4];
            #pragma unroll
            for (int mt = 0; mt < 2; mt++) {
                uint32_t base = cur + 2u * ((wm*32 + mt*16) * SROW + ks*16 + aoff);
                ldsm4(ahi[mt], base + SM_AHI);
                ldsm4(alo[mt], base + SM_ALO);
            }
            #pragma unroll
            for (int np = 0; np < 2; np++) {
                uint32_t base = cur + 2u * ((wn*32 + np*16) * SROW + ks*16 + boff);
                ldsm4(bhi[np], base + SM_BHI);
                ldsm4(blo[np], base + SM_BLO);
            }
            #pragma unroll
            for (int mt = 0; mt < 2; mt++)
                #pragma unroll
                for (int nt = 0; nt < 4; nt++) {
                    const uint32_t* bh = &bhi[nt >> 1][(nt & 1) * 2];
                    const uint32_t* bl = &blo[nt >> 1][(nt & 1) * 2];
                    mma16816(acc[mt][nt], ahi[mt], bh);
                    mma16816(acc[mt][nt], alo[mt], bh);
                    mma16816(acc[mt][nt], ahi[mt], bl);
                }
        }
        __syncthreads();
    }

    // ---- epilogue: bias + tanh-jet ----
    float bb[4][2];
    #pragma unroll
    for (int nt = 0; nt < 4; nt++)
        #pragma unroll
        for (int j = 0; j < 2; j++)
            bb[nt][j] = __ldg(&bias[col0 + wn*32 + nt*8 + (lane & 3)*2 + j]);

    const int role = (lane >> 2) & 3;
    const int srcL = (lane & ~15) | (lane & 3);

    if (blockIdx.y < INT_TILES) {
        #pragma unroll
        for (int mt = 0; mt < 2; mt++)
            #pragma unroll
            for (int h = 0; h < 2; h++) {
                const int grow = row0 + wm*32 + mt*16 + (lane >> 2) + 8*h;
                #pragma unroll
                for (int nt = 0; nt < 4; nt++) {
                    float o[2];
                    #pragma unroll
                    for (int j = 0; j < 2; j++) {
                        float x  = acc[mt][nt][h*2 + j];
                        float v  = __shfl_sync(0xFFFFFFFFu, x, srcL);
                        float p0 = __shfl_sync(0xFFFFFFFFu, x, srcL + 4);
                        float p1 = __shfl_sync(0xFFFFFFFFu, x, srcL + 8);
                        float y  = tanhf(v + bb[nt][j]);
                        float s  = 1.0f - y*y;
                        float r;
                        if      (role == 0) r = y;
                        else if (role == 1) r = s * p0;
                        else if (role == 2) r = s * p1;
                        else                r = fmaf(s, x, -2.0f * y * s * (p0*p0 + p1*p1));
                        o[j] = r;
                    }
                    const int colb = col0 + wn*32 + nt*8 + (lane & 3)*2;
                    if (MODE == 1) {
                        uint32_t h0, l0, h1, l1;
                        hsplit(o[0], h0, l0);
                        hsplit(o[1], h1, l1);
                        size_t off = (size_t)grow * HID + colb;
                        *(uint32_t*)&g_A2hi[off] = h0 | (h1 << 16);
                        *(uint32_t*)&g_A2lo[off] = l0 | (l1 << 16);
                    } else if (role == 3) {
                        *(float2*)&g_S[(size_t)(grow >> 2) * HID + colb] = make_float2(o[0], o[1]);
                    }
                }
            }
    } else {
        #pragma unroll
        for (int mt = 0; mt < 2; mt++)
            #pragma unroll
            for (int h = 0; h < 2; h++) {
                const int grow = row0 + wm*32 + mt*16 + (lane >> 2) + 8*h;
                if (grow < M_ROWS) {
                    #pragma unroll
                    for (int nt = 0; nt < 4; nt++) {
                        float o0 = tanhf(acc[mt][nt][h*2 + 0] + bb[nt][0]);
                        float o1 = tanhf(acc[mt][nt][h*2 + 1] + bb[nt][1]);
                        const int colb = col0 + wn*32 + nt*8 + (lane & 3)*2;
                        if (MODE == 1) {
                            uint32_t h0, l0, h1, l1;
                            hsplit(o0, h0, l0);
                            hsplit(o1, h1, l1);
                            size_t off = (size_t)grow * HID + colb;
                            *(uint32_t*)&g_A2hi[off] = h0 | (h1 << 16);
                            *(uint32_t*)&g_A2lo[off] = l0 | (l1 << 16);
                        } else {
                            *(float2*)&g_Yb[(size_t)(grow - BROW) * HID + colb] = make_float2(o0, o1);
                        }
                    }
                }
            }
    }
}

// ---------------------------------------------------------------------------
// Final reductions (unchanged, proven).
// ---------------------------------------------------------------------------
__global__ void k_final_interior(const float* __restrict__ xi, const float* __restrict__ W3)
{
    int warp = threadIdx.x >> 5;
    int lane = threadIdx.x & 31;
    int p = blockIdx.x * 8 + warp;

    float val = 0.0f;
    if (p < N_INT) {
        const float* row = &g_S[(size_t)p * HID];
        float acc = 0.0f;
        #pragma unroll 4
        for (int j = lane; j < HID; j += 32) acc = fmaf(row[j], W3[j], acc);
        #pragma unroll
        for (int o = 16; o; o >>= 1) acc += __shfl_xor_sync(0xFFFFFFFFu, acc, o);
        if (lane == 0) {
            const float PI = 3.14159265358979323846f;
            float xx = xi[2*p], yy = xi[2*p+1];
            float sy2 = sinf(PI*yy*yy), cy2 = cosf(PI*yy*yy), sx = sinf(PI*xx);
            float f = -PI*PI*(1.0f + 4.0f*yy*yy)*sx*sy2 + 2.0f*PI*sx*cy2;
            float r = acc - f;
            val = r * r;
        }
    }
    __shared__ float sh[8];
    if (lane == 0) sh[warp] = val;
    __syncthreads();
    if (threadIdx.x == 0) {
        float s = 0.0f;
        #pragma unroll
        for (int i = 0; i < 8; i++) s += sh[i];
        g_partial_i[blockIdx.x] = s;
    }
}

__global__ void k_final_boundary(const float* __restrict__ W3, const float* __restrict__ b3)
{
    int warp = threadIdx.x >> 5;
    int lane = threadIdx.x & 31;
    int p = blockIdx.x * 8 + warp;

    float val = 0.0f;
    if (p < N_B) {
        const float* row = &g_Yb[(size_t)p * HID];
        float acc = 0.0f;
        #pragma unroll 4
        for (int j = lane; j < HID; j += 32) acc = fmaf(row[j], W3[j], acc);
        #pragma unroll
        for (int o = 16; o; o >>= 1) acc += __shfl_xor_sync(0xFFFFFFFFu, acc, o);
        if (lane == 0) {
            float u = acc + b3[0];
            val = u * u;
        }
    }
    __shared__ float sh[8];
    if (lane == 0) sh[warp] = val;
    __syncthreads();
    if (threadIdx.x == 0) {
        float s = 0.0f;
        #pragma unroll
        for (int i = 0; i < 8; i++) s += sh[i];
        g_partial_b[blockIdx.x] = s;
    }
}

__global__ void k_combine(float* __restrict__ out)
{
    __shared__ float sh[256];
    int t = threadIdx.x;

    float si = 0.0f;
    for (int i = t; i < 2500; i += 256) si += g_partial_i[i];
    sh[t] = si;
    __syncthreads();
    for (int o = 128; o; o >>= 1) { if (t < o) sh[t] += sh[t + o]; __syncthreads(); }
    float interior_sum = sh[0];
    __syncthreads();

    float sb = 0.0f;
    for (int i = t; i < 100; i += 256) sb += g_partial_b[i];
    sh[t] = sb;
    __syncthreads();
    for (int o = 128; o; o >>= 1) { if (t < o) sh[t] += sh[t + o]; __syncthreads(); }

    if (t == 0) {
        float interior_loss = interior_sum / (float)N_INT;
        float boundary_loss = sh[0] / (float)N_B;
        out[0] = ALPHA * interior_loss + boundary_loss;
        out[1] = interior_loss;
        out[2] = boundary_loss;
    }
}

// ---------------------------------------------------------------------------
extern "C" void kernel_launch(void* const* d_in, const int* in_sizes, int n_in,
                              void* d_out, int out_size)
{
    const float* xi = (const float*)d_in[0];
    const float* xb = (const float*)d_in[1];
    const float* W0 = (const float*)d_in[2];
    const float* b0 = (const float*)d_in[3];
    const float* W1 = (const float*)d_in[4];
    const float* b1 = (const float*)d_in[5];
    const float* W2 = (const float*)d_in[6];
    const float* b2 = (const float*)d_in[7];
    const float* W3 = (const float*)d_in[8];
    const float* b3 = (const float*)d_in[9];

    cudaFuncSetAttribute(k_mma<1>, cudaFuncAttributeMaxDynamicSharedMemorySize, SMEM_DYN);
    cudaFuncSetAttribute(k_mma<2>, cudaFuncAttributeMaxDynamicSharedMemorySize, SMEM_DYN);

    dim3 tgrid(16, 16), tblock(32, 32);
    dim3 mma_grid(4, M_TILES);

    k_layer0<<<N_INT + N_B, 256>>>(xi, xb, W0, b0);
    k_transpose<1><<<tgrid, tblock>>>(W1);
    k_transpose<2><<<tgrid, tblock>>>(W2);
    k_mma<1><<<mma_grid, 512, SMEM_DYN>>>(b1);
    k_mma<2><<<mma_grid, 512, SMEM_DYN>>>(b2);
    k_final_interior<<<(N_INT + 7) / 8, 256>>>(xi, W3);
    k_final_boundary<<<(N_B + 7) / 8, 256>>>(W3, b3);
    k_combine<<<1, 256>>>((float*)d_out);
}

// round 10
// speedup vs baseline: 2.2135x; 1.0302x over previous
#include <cuda_runtime.h>
#include <cuda_fp16.h>
#include <math.h>
#include <stdint.h>

#define N_INT 20000
#define N_B   800
#define HID   512
#define BROW  (4*N_INT)              // 80000
#define M_ROWS (BROW + N_B)          // 80800
#define M_TILES 632
#define INT_TILES 625
#define M_PAD (M_TILES*128)          // 80896 (pad rows stay zero forever)
#define ALPHA 0.01f
#define NCH 16                       // 512/32 k-chunks

// smem: per stage: Ahi/Alo/Bhi/Blo, each 128 rows x 40 halves (pad -> ldmatrix conflict-free)
#define SROW 40
#define SM_AHI 0
#define SM_ALO 10240
#define SM_BHI 20480
#define SM_BLO 30720
#define STAGE  40960
#define NSTAGE 3
#define SMEM_DYN (NSTAGE*STAGE)

// Activations as hi/lo fp16 pairs (Markidis split). Ping-pong A -> A2.
__device__ __half g_Ahi [(size_t)M_PAD * HID];
__device__ __half g_Alo [(size_t)M_PAD * HID];
__device__ __half g_A2hi[(size_t)M_PAD * HID];
__device__ __half g_A2lo[(size_t)M_PAD * HID];
__device__ __half g_W1hi[HID * HID];   // [n][k]
__device__ __half g_W1lo[HID * HID];
__device__ __half g_W2hi[HID * HID];
__device__ __half g_W2lo[HID * HID];
__device__ float  g_S [(size_t)N_INT * HID];
__device__ float  g_Yb[(size_t)N_B * HID];
__device__ float  g_partial_i[2500];
__device__ float  g_partial_b[100];

// ------------------------------- helpers -----------------------------------
static __device__ __forceinline__ uint32_t smem_u32(const void* p) {
    uint32_t a;
    asm("{ .reg .u64 t; cvta.to.shared.u64 t, %1; cvt.u32.u64 %0, t; }" : "=r"(a) : "l"(p));
    return a;
}
static __device__ __forceinline__ void cp16(uint32_t dst, const void* src) {
    asm volatile("cp.async.cg.shared.global [%0], [%1], 16;" :: "r"(dst), "l"(src));
}
static __device__ __forceinline__ void ldsm4(uint32_t* r, uint32_t addr) {
    asm volatile("ldmatrix.sync.aligned.m8n8.x4.shared.b16 {%0,%1,%2,%3}, [%4];"
                 : "=r"(r[0]), "=r"(r[1]), "=r"(r[2]), "=r"(r[3]) : "r"(addr));
}
static __device__ __forceinline__ void mma16816(float* d, const uint32_t* a, const uint32_t* b) {
    asm volatile(
        "mma.sync.aligned.m16n8k16.row.col.f32.f16.f16.f32 "
        "{%0,%1,%2,%3}, {%4,%5,%6,%7}, {%8,%9}, {%0,%1,%2,%3};"
        : "+f"(d[0]), "+f"(d[1]), "+f"(d[2]), "+f"(d[3])
        : "r"(a[0]), "r"(a[1]), "r"(a[2]), "r"(a[3]), "r"(b[0]), "r"(b[1]));
}
static __device__ __forceinline__ void hsplit(float x, uint32_t& h, uint32_t& l) {
    __half hh = __float2half_rn(x);
    float  r  = x - __half2float(hh);
    __half ll = __float2half_rn(r);
    h = __half_as_ushort(hh);
    l = __half_as_ushort(ll);
}
// load the 32 fragment regs (2 A mt-tiles hi/lo + 2 B np-tiles hi/lo) for one ks
static __device__ __forceinline__ void load_frags(
    uint32_t cur, int ks, int wm, int wn, int aoff, int boff,
    uint32_t ahi[2][4], uint32_t alo[2][4], uint32_t bhi[2][4], uint32_t blo[2][4])
{
    #pragma unroll
    for (int mt = 0; mt < 2; mt++) {
        uint32_t base = cur + 2u * ((wm*32 + mt*16) * SROW + ks*16 + aoff);
        ldsm4(ahi[mt], base + SM_AHI);
        ldsm4(alo[mt], base + SM_ALO);
    }
    #pragma unroll
    for (int np = 0; np < 2; np++) {
        uint32_t base = cur + 2u * ((wn*32 + np*16) * SROW + ks*16 + boff);
        ldsm4(bhi[np], base + SM_BHI);
        ldsm4(blo[np], base + SM_BLO);
    }
}
static __device__ __forceinline__ void do_mmas(
    float acc[2][4][4],
    uint32_t ahi[2][4], uint32_t alo[2][4], uint32_t bhi[2][4], uint32_t blo[2][4])
{
    #pragma unroll
    for (int mt = 0; mt < 2; mt++)
        #pragma unroll
        for (int nt = 0; nt < 4; nt++) {
            const uint32_t* bh = &bhi[nt >> 1][(nt & 1) * 2];
            const uint32_t* bl = &blo[nt >> 1][(nt & 1) * 2];
            mma16816(acc[mt][nt], ahi[mt], bh);
            mma16816(acc[mt][nt], alo[mt], bh);
            mma16816(acc[mt][nt], ahi[mt], bl);
        }
}

// ---------------------------------------------------------------------------
// Layer 0: x -> 512 with jet init, interleaved hi/lo fp16 output.
// ---------------------------------------------------------------------------
__global__ void k_layer0(const float* __restrict__ xi, const float* __restrict__ xb,
                         const float* __restrict__ W0, const float* __restrict__ b0)
{
    const int p = blockIdx.x;
    const int j = threadIdx.x * 2;

    float w0a = W0[j],       w0b = W0[j+1];
    float w1a = W0[HID + j], w1b = W0[HID + j + 1];
    float b0a = b0[j],       b0b = b0[j+1];

    if (p < N_INT) {
        float x0 = xi[2*p], x1 = xi[2*p+1];
        float va = fmaf(x0, w0a, fmaf(x1, w1a, b0a));
        float vb = fmaf(x0, w0b, fmaf(x1, w1b, b0b));
        float ya = tanhf(va), yb = tanhf(vb);
        float sa = 1.0f - ya*ya, sb = 1.0f - yb*yb;
        float vals[4][2] = {
            { ya, yb },
            { sa * w0a, sb * w0b },
            { sa * w1a, sb * w1b },
            { -2.0f*ya*sa*(w0a*w0a + w1a*w1a), -2.0f*yb*sb*(w0b*w0b + w1b*w1b) }
        };
        #pragma unroll
        for (int t = 0; t < 4; t++) {
            uint32_t h0, l0, h1, l1;
            hsplit(vals[t][0], h0, l0);
            hsplit(vals[t][1], h1, l1);
            size_t off = (size_t)(4*p + t) * HID + j;
            *(uint32_t*)&g_Ahi[off] = h0 | (h1 << 16);
            *(uint32_t*)&g_Alo[off] = l0 | (l1 << 16);
        }
    } else {
        int q = p - N_INT;
        float x0 = xb[2*q], x1 = xb[2*q+1];
        float va = fmaf(x0, w0a, fmaf(x1, w1a, b0a));
        float vb = fmaf(x0, w0b, fmaf(x1, w1b, b0b));
        float ya = tanhf(va), yb = tanhf(vb);
        uint32_t h0, l0, h1, l1;
        hsplit(ya, h0, l0);
        hsplit(yb, h1, l1);
        size_t off = (size_t)(BROW + q) * HID + j;
        *(uint32_t*)&g_Ahi[off] = h0 | (h1 << 16);
        *(uint32_t*)&g_Alo[off] = l0 | (l1 << 16);
    }
}

// ---------------------------------------------------------------------------
// Weight transpose + fp16 split: Wt*[n][k] = split(W[k][n])
// ---------------------------------------------------------------------------
template<int WHICH>
__global__ void k_transpose(const float* __restrict__ W)
{
    __half* __restrict__ Whi = (WHICH == 1) ? g_W1hi : g_W2hi;
    __half* __restrict__ Wlo = (WHICH == 1) ? g_W1lo : g_W2lo;
    __shared__ float ts[32][33];
    int n0 = blockIdx.x * 32, k0 = blockIdx.y * 32;
    ts[threadIdx.y][threadIdx.x] = W[(size_t)(k0 + threadIdx.y) * HID + n0 + threadIdx.x];
    __syncthreads();
    float v = ts[threadIdx.x][threadIdx.y];   // = W[k0+tx][n0+ty]
    uint32_t h, l;
    hsplit(v, h, l);
    size_t off = (size_t)(n0 + threadIdx.y) * HID + k0 + threadIdx.x;
    Whi[off] = __ushort_as_half((unsigned short)h);
    Wlo[off] = __ushort_as_half((unsigned short)l);
}

// ---------------------------------------------------------------------------
// fp16 3-split GEMM via mma.sync + fused bias/tanh-jet epilogue.
// 3-stage cp.async pipeline + register-double-buffered ldmatrix fragments.
// MODE 1: jet(A @ W1 + b1) -> g_A2hi/lo (full interleaved)
// MODE 2: jet(A2 @ W2 + b2) -> S rows (fp32) to g_S, boundary rows to g_Yb
// BM=128, BN=128, BK=32, 512 thr (16 warps in 4x4 grid, 32x32 warp tiles).
// ---------------------------------------------------------------------------
template<int MODE>
__global__ __launch_bounds__(512, 1)
void k_mma(const float* __restrict__ bias)
{
    const __half* __restrict__ Ahi = (MODE == 1) ? g_Ahi : g_A2hi;
    const __half* __restrict__ Alo = (MODE == 1) ? g_Alo : g_A2lo;
    const __half* __restrict__ Whi = (MODE == 1) ? g_W1hi : g_W2hi;
    const __half* __restrict__ Wlo = (MODE == 1) ? g_W1lo : g_W2lo;

    extern __shared__ char smem[];
    const uint32_t sbase = smem_u32(smem);

    const int tid  = threadIdx.x;
    const int lane = tid & 31;
    const int wid  = tid >> 5;
    const int wm   = wid >> 2;        // 0..3 : rows wm*32
    const int wn   = wid & 3;         // 0..3 : cols wn*32
    const int row0 = blockIdx.y * 128;
    const int col0 = blockIdx.x * 128;

    // ldmatrix lane offsets (in halves)
    const int grp = lane >> 3, idx = lane & 7;
    const int aoff = ((grp & 1) * 8 + idx) * SROW + (grp >> 1) * 8;
    const int boff = ((grp >> 1) * 8 + idx) * SROW + (grp & 1) * 8;

    float acc[2][4][4];
    #pragma unroll
    for (int mt = 0; mt < 2; mt++)
        #pragma unroll
        for (int nt = 0; nt < 4; nt++)
            #pragma unroll
            for (int q = 0; q < 4; q++) acc[mt][nt][q] = 0.0f;

    // prefetch: 512 threads, 1 x 16B per thread per tile
    const int fr = tid >> 2;            // 0..127
    const int fs = (tid & 3) * 8;       // 0,8,16,24 halves
    auto prefetch = [&](int c) {
        uint32_t st = sbase + (uint32_t)(c % NSTAGE) * STAGE;
        size_t ga = (size_t)(row0 + fr) * HID + c * 32 + fs;
        size_t gb = (size_t)(col0 + fr) * HID + c * 32 + fs;
        uint32_t o = (uint32_t)(fr * SROW + fs) * 2;
        cp16(st + SM_AHI + o, Ahi + ga);
        cp16(st + SM_ALO + o, Alo + ga);
        cp16(st + SM_BHI + o, Whi + gb);
        cp16(st + SM_BLO + o, Wlo + gb);
        asm volatile("cp.async.commit_group;" ::: "memory");
    };

    prefetch(0);
    prefetch(1);

    uint32_t fa_hi[2][2][4], fa_lo[2][2][4], fb_hi[2][2][4], fb_lo[2][2][4];

    for (int c = 0; c < NCH; c++) {
        if (c == NCH - 1) asm volatile("cp.async.wait_group 0;" ::: "memory");
        else              asm volatile("cp.async.wait_group 1;" ::: "memory");
        __syncthreads();

        // safe to overwrite stage (c+2)%NSTAGE: its last readers finished at iter c-1
        if (c + 2 < NCH) prefetch(c + 2);

        const uint32_t cur = sbase + (uint32_t)(c % NSTAGE) * STAGE;
        // ks=0 frags into buffer 0, then overlap: load ks=1 while ks=0 MMAs run
        load_frags(cur, 0, wm, wn, aoff, boff, fa_hi[0], fa_lo[0], fb_hi[0], fb_lo[0]);
        load_frags(cur, 1, wm, wn, aoff, boff, fa_hi[1], fa_lo[1], fb_hi[1], fb_lo[1]);
        do_mmas(acc, fa_hi[0], fa_lo[0], fb_hi[0], fb_lo[0]);
        do_mmas(acc, fa_hi[1], fa_lo[1], fb_hi[1], fb_lo[1]);
        __syncthreads();
    }

    // ---- epilogue: bias + tanh-jet ----
    float bb[4][2];
    #pragma unroll
    for (int nt = 0; nt < 4; nt++)
        #pragma unroll
        for (int j = 0; j < 2; j++)
            bb[nt][j] = __ldg(&bias[col0 + wn*32 + nt*8 + (lane & 3)*2 + j]);

    const int role = (lane >> 2) & 3;
    const int srcL = (lane & ~15) | (lane & 3);

    if (blockIdx.y < INT_TILES) {
        #pragma unroll
        for (int mt = 0; mt < 2; mt++)
            #pragma unroll
            for (int h = 0; h < 2; h++) {
                const int grow = row0 + wm*32 + mt*16 + (lane >> 2) + 8*h;
                #pragma unroll
                for (int nt = 0; nt < 4; nt++) {
                    float o[2];
                    #pragma unroll
                    for (int j = 0; j < 2; j++) {
                        float x  = acc[mt][nt][h*2 + j];
                        float v  = __shfl_sync(0xFFFFFFFFu, x, srcL);
                        float p0 = __shfl_sync(0xFFFFFFFFu, x, srcL + 4);
                        float p1 = __shfl_sync(0xFFFFFFFFu, x, srcL + 8);
                        float y  = tanhf(v + bb[nt][j]);
                        float s  = 1.0f - y*y;
                        float r;
                        if      (role == 0) r = y;
                        else if (role == 1) r = s * p0;
                        else if (role == 2) r = s * p1;
                        else                r = fmaf(s, x, -2.0f * y * s * (p0*p0 + p1*p1));
                        o[j] = r;
                    }
                    const int colb = col0 + wn*32 + nt*8 + (lane & 3)*2;
                    if (MODE == 1) {
                        uint32_t h0, l0, h1, l1;
                        hsplit(o[0], h0, l0);
                        hsplit(o[1], h1, l1);
                        size_t off = (size_t)grow * HID + colb;
                        *(uint32_t*)&g_A2hi[off] = h0 | (h1 << 16);
                        *(uint32_t*)&g_A2lo[off] = l0 | (l1 << 16);
                    } else if (role == 3) {
                        *(float2*)&g_S[(size_t)(grow >> 2) * HID + colb] = make_float2(o[0], o[1]);
                    }
                }
            }
    } else {
        #pragma unroll
        for (int mt = 0; mt < 2; mt++)
            #pragma unroll
            for (int h = 0; h < 2; h++) {
                const int grow = row0 + wm*32 + mt*16 + (lane >> 2) + 8*h;
                if (grow < M_ROWS) {
                    #pragma unroll
                    for (int nt = 0; nt < 4; nt++) {
                        float o0 = tanhf(acc[mt][nt][h*2 + 0] + bb[nt][0]);
                        float o1 = tanhf(acc[mt][nt][h*2 + 1] + bb[nt][1]);
                        const int colb = col0 + wn*32 + nt*8 + (lane & 3)*2;
                        if (MODE == 1) {
                            uint32_t h0, l0, h1, l1;
                            hsplit(o0, h0, l0);
                            hsplit(o1, h1, l1);
                            size_t off = (size_t)grow * HID + colb;
                            *(uint32_t*)&g_A2hi[off] = h0 | (h1 << 16);
                            *(uint32_t*)&g_A2lo[off] = l0 | (l1 << 16);
                        } else {
                            *(float2*)&g_Yb[(size_t)(grow - BROW) * HID + colb] = make_float2(o0, o1);
                        }
                    }
                }
            }
    }
}

// ---------------------------------------------------------------------------
// Final reductions (unchanged, proven).
// ---------------------------------------------------------------------------
__global__ void k_final_interior(const float* __restrict__ xi, const float* __restrict__ W3)
{
    int warp = threadIdx.x >> 5;
    int lane = threadIdx.x & 31;
    int p = blockIdx.x * 8 + warp;

    float val = 0.0f;
    if (p < N_INT) {
        const float* row = &g_S[(size_t)p * HID];
        float acc = 0.0f;
        #pragma unroll 4
        for (int j = lane; j < HID; j += 32) acc = fmaf(row[j], W3[j], acc);
        #pragma unroll
        for (int o = 16; o; o >>= 1) acc += __shfl_xor_sync(0xFFFFFFFFu, acc, o);
        if (lane == 0) {
            const float PI = 3.14159265358979323846f;
            float xx = xi[2*p], yy = xi[2*p+1];
            float sy2 = sinf(PI*yy*yy), cy2 = cosf(PI*yy*yy), sx = sinf(PI*xx);
            float f = -PI*PI*(1.0f + 4.0f*yy*yy)*sx*sy2 + 2.0f*PI*sx*cy2;
            float r = acc - f;
            val = r * r;
        }
    }
    __shared__ float sh[8];
    if (lane == 0) sh[warp] = val;
    __syncthreads();
    if (threadIdx.x == 0) {
        float s = 0.0f;
        #pragma unroll
        for (int i = 0; i < 8; i++) s += sh[i];
        g_partial_i[blockIdx.x] = s;
    }
}

__global__ void k_final_boundary(const float* __restrict__ W3, const float* __restrict__ b3)
{
    int warp = threadIdx.x >> 5;
    int lane = threadIdx.x & 31;
    int p = blockIdx.x * 8 + warp;

    float val = 0.0f;
    if (p < N_B) {
        const float* row = &g_Yb[(size_t)p * HID];
        float acc = 0.0f;
        #pragma unroll 4
        for (int j = lane; j < HID; j += 32) acc = fmaf(row[j], W3[j], acc);
        #pragma unroll
        for (int o = 16; o; o >>= 1) acc += __shfl_xor_sync(0xFFFFFFFFu, acc, o);
        if (lane == 0) {
            float u = acc + b3[0];
            val = u * u;
        }
    }
    __shared__ float sh[8];
    if (lane == 0) sh[warp] = val;
    __syncthreads();
    if (threadIdx.x == 0) {
        float s = 0.0f;
        #pragma unroll
        for (int i = 0; i < 8; i++) s += sh[i];
        g_partial_b[blockIdx.x] = s;
    }
}

__global__ void k_combine(float* __restrict__ out)
{
    __shared__ float sh[256];
    int t = threadIdx.x;

    float si = 0.0f;
    for (int i = t; i < 2500; i += 256) si += g_partial_i[i];
    sh[t] = si;
    __syncthreads();
    for (int o = 128; o; o >>= 1) { if (t < o) sh[t] += sh[t + o]; __syncthreads(); }
    float interior_sum = sh[0];
    __syncthreads();

    float sb = 0.0f;
    for (int i = t; i < 100; i += 256) sb += g_partial_b[i];
    sh[t] = sb;
    __syncthreads();
    for (int o = 128; o; o >>= 1) { if (t < o) sh[t] += sh[t + o]; __syncthreads(); }

    if (t == 0) {
        float interior_loss = interior_sum / (float)N_INT;
        float boundary_loss = sh[0] / (float)N_B;
        out[0] = ALPHA * interior_loss + boundary_loss;
        out[1] = interior_loss;
        out[2] = boundary_loss;
    }
}

// ---------------------------------------------------------------------------
extern "C" void kernel_launch(void* const* d_in, const int* in_sizes, int n_in,
                              void* d_out, int out_size)
{
    const float* xi = (const float*)d_in[0];
    const float* xb = (const float*)d_in[1];
    const float* W0 = (const float*)d_in[2];
    const float* b0 = (const float*)d_in[3];
    const float* W1 = (const float*)d_in[4];
    const float* b1 = (const float*)d_in[5];
    const float* W2 = (const float*)d_in[6];
    const float* b2 = (const float*)d_in[7];
    const float* W3 = (const float*)d_in[8];
    const float* b3 = (const float*)d_in[9];

    cudaFuncSetAttribute(k_mma<1>, cudaFuncAttributeMaxDynamicSharedMemorySize, SMEM_DYN);
    cudaFuncSetAttribute(k_mma<2>, cudaFuncAttributeMaxDynamicSharedMemorySize, SMEM_DYN);

    dim3 tgrid(16, 16), tblock(32, 32);
    dim3 mma_grid(4, M_TILES);

    k_layer0<<<N_INT + N_B, 256>>>(xi, xb, W0, b0);
    k_transpose<1><<<tgrid, tblock>>>(W1);
    k_transpose<2><<<tgrid, tblock>>>(W2);
    k_mma<1><<<mma_grid, 512, SMEM_DYN>>>(b1);
    k_mma<2><<<mma_grid, 512, SMEM_DYN>>>(b2);
    k_final_interior<<<(N_INT + 7) / 8, 256>>>(xi, W3);
    k_final_boundary<<<(N_B + 7) / 8, 256>>>(W3, b3);
    k_combine<<<1, 256>>>((float*)d_out);
}

// round 13
// speedup vs baseline: 2.2167x; 1.0014x over previous
#include <cuda_runtime.h>
#include <cuda_fp16.h>
#include <math.h>
#include <stdint.h>

#define N_INT 20000
#define N_B   800
#define HID   512
#define BROW  (4*N_INT)              // 80000
#define M_ROWS (BROW + N_B)          // 80800
#define M_TILES 1263                 // ceil(80800/64)
#define INT_TILES 1250               // 80000/64 : tiles below are pure interior
#define M_PAD (M_TILES*64)           // 80832 (pad rows stay zero forever)
#define ALPHA 0.01f
#define NCH 16                       // 512/32 k-chunks

// smem per stage: Ahi/Alo (64 x 40 halves) + Bhi/Blo (128 x 40 halves)
#define SROW 40
#define SM_AHI 0
#define SM_ALO 5120
#define SM_BHI 10240
#define SM_BLO 20480
#define STAGE  30720
#define NSTAGE 3
#define SMEM_DYN (NSTAGE*STAGE)      // 92160 B -> 2 CTAs/SM

// Activations as hi/lo fp16 pairs (Markidis split). Ping-pong A -> A2.
__device__ __half g_Ahi [(size_t)M_PAD * HID];
__device__ __half g_Alo [(size_t)M_PAD * HID];
__device__ __half g_A2hi[(size_t)M_PAD * HID];
__device__ __half g_A2lo[(size_t)M_PAD * HID];
__device__ __half g_W1hi[HID * HID];   // [n][k]
__device__ __half g_W1lo[HID * HID];
__device__ __half g_W2hi[HID * HID];
__device__ __half g_W2lo[HID * HID];
__device__ float  g_S [(size_t)N_INT * HID];
__device__ float  g_Yb[(size_t)N_B * HID];
__device__ float  g_partial_i[2500];
__device__ float  g_partial_b[100];

// ------------------------------- helpers -----------------------------------
static __device__ __forceinline__ uint32_t smem_u32(const void* p) {
    uint32_t a;
    asm("{ .reg .u64 t; cvta.to.shared.u64 t, %1; cvt.u32.u64 %0, t; }" : "=r"(a) : "l"(p));
    return a;
}
static __device__ __forceinline__ void cp16(uint32_t dst, const void* src) {
    asm volatile("cp.async.cg.shared.global [%0], [%1], 16;" :: "r"(dst), "l"(src));
}
static __device__ __forceinline__ void ldsm4(uint32_t* r, uint32_t addr) {
    asm volatile("ldmatrix.sync.aligned.m8n8.x4.shared.b16 {%0,%1,%2,%3}, [%4];"
                 : "=r"(r[0]), "=r"(r[1]), "=r"(r[2]), "=r"(r[3]) : "r"(addr));
}
static __device__ __forceinline__ void mma16816(float* d, const uint32_t* a, const uint32_t* b) {
    asm volatile(
        "mma.sync.aligned.m16n8k16.row.col.f32.f16.f16.f32 "
        "{%0,%1,%2,%3}, {%4,%5,%6,%7}, {%8,%9}, {%0,%1,%2,%3};"
        : "+f"(d[0]), "+f"(d[1]), "+f"(d[2]), "+f"(d[3])
        : "r"(a[0]), "r"(a[1]), "r"(a[2]), "r"(a[3]), "r"(b[0]), "r"(b[1]));
}
static __device__ __forceinline__ void hsplit(float x, uint32_t& h, uint32_t& l) {
    __half hh = __float2half_rn(x);
    float  r  = x - __half2float(hh);
    __half ll = __float2half_rn(r);
    h = __half_as_ushort(hh);
    l = __half_as_ushort(ll);
}
static __device__ __forceinline__ void load_frags(
    uint32_t cur, int ks, int wm, int wn, int aoff, int boff,
    uint32_t ahi[2][4], uint32_t alo[2][4], uint32_t bhi[2][4], uint32_t blo[2][4])
{
    #pragma unroll
    for (int mt = 0; mt < 2; mt++) {
        uint32_t base = cur + 2u * ((wm*32 + mt*16) * SROW + ks*16 + aoff);
        ldsm4(ahi[mt], base + SM_AHI);
        ldsm4(alo[mt], base + SM_ALO);
    }
    #pragma unroll
    for (int np = 0; np < 2; np++) {
        uint32_t base = cur + 2u * ((wn*32 + np*16) * SROW + ks*16 + boff);
        ldsm4(bhi[np], base + SM_BHI);
        ldsm4(blo[np], base + SM_BLO);
    }
}
static __device__ __forceinline__ void do_mmas(
    float acc[2][4][4],
    uint32_t ahi[2][4], uint32_t alo[2][4], uint32_t bhi[2][4], uint32_t blo[2][4])
{
    #pragma unroll
    for (int mt = 0; mt < 2; mt++)
        #pragma unroll
        for (int nt = 0; nt < 4; nt++) {
            const uint32_t* bh = &bhi[nt >> 1][(nt & 1) * 2];
            const uint32_t* bl = &blo[nt >> 1][(nt & 1) * 2];
            mma16816(acc[mt][nt], ahi[mt], bh);
            mma16816(acc[mt][nt], alo[mt], bh);
            mma16816(acc[mt][nt], ahi[mt], bl);
        }
}

// ---------------------------------------------------------------------------
// Layer 0: x -> 512 with jet init, interleaved hi/lo fp16 output.
// ---------------------------------------------------------------------------
__global__ void k_layer0(const float* __restrict__ xi, const float* __restrict__ xb,
                         const float* __restrict__ W0, const float* __restrict__ b0)
{
    const int p = blockIdx.x;
    const int j = threadIdx.x * 2;

    float w0a = W0[j],       w0b = W0[j+1];
    float w1a = W0[HID + j], w1b = W0[HID + j + 1];
    float b0a = b0[j],       b0b = b0[j+1];

    if (p < N_INT) {
        float x0 = xi[2*p], x1 = xi[2*p+1];
        float va = fmaf(x0, w0a, fmaf(x1, w1a, b0a));
        float vb = fmaf(x0, w0b, fmaf(x1, w1b, b0b));
        float ya = tanhf(va), yb = tanhf(vb);
        float sa = 1.0f - ya*ya, sb = 1.0f - yb*yb;
        float vals[4][2] = {
            { ya, yb },
            { sa * w0a, sb * w0b },
            { sa * w1a, sb * w1b },
            { -2.0f*ya*sa*(w0a*w0a + w1a*w1a), -2.0f*yb*sb*(w0b*w0b + w1b*w1b) }
        };
        #pragma unroll
        for (int t = 0; t < 4; t++) {
            uint32_t h0, l0, h1, l1;
            hsplit(vals[t][0], h0, l0);
            hsplit(vals[t][1], h1, l1);
            size_t off = (size_t)(4*p + t) * HID + j;
            *(uint32_t*)&g_Ahi[off] = h0 | (h1 << 16);
            *(uint32_t*)&g_Alo[off] = l0 | (l1 << 16);
        }
    } else {
        int q = p - N_INT;
        float x0 = xb[2*q], x1 = xb[2*q+1];
        float va = fmaf(x0, w0a, fmaf(x1, w1a, b0a));
        float vb = fmaf(x0, w0b, fmaf(x1, w1b, b0b));
        float ya = tanhf(va), yb = tanhf(vb);
        uint32_t h0, l0, h1, l1;
        hsplit(ya, h0, l0);
        hsplit(yb, h1, l1);
        size_t off = (size_t)(BROW + q) * HID + j;
        *(uint32_t*)&g_Ahi[off] = h0 | (h1 << 16);
        *(uint32_t*)&g_Alo[off] = l0 | (l1 << 16);
    }
}

// ---------------------------------------------------------------------------
// Weight transpose + fp16 split: Wt*[n][k] = split(W[k][n])
// ---------------------------------------------------------------------------
template<int WHICH>
__global__ void k_transpose(const float* __restrict__ W)
{
    __half* __restrict__ Whi = (WHICH == 1) ? g_W1hi : g_W2hi;
    __half* __restrict__ Wlo = (WHICH == 1) ? g_W1lo : g_W2lo;
    __shared__ float ts[32][33];
    int n0 = blockIdx.x * 32, k0 = blockIdx.y * 32;
    ts[threadIdx.y][threadIdx.x] = W[(size_t)(k0 + threadIdx.y) * HID + n0 + threadIdx.x];
    __syncthreads();
    float v = ts[threadIdx.x][threadIdx.y];   // = W[k0+tx][n0+ty]
    uint32_t h, l;
    hsplit(v, h, l);
    size_t off = (size_t)(n0 + threadIdx.y) * HID + k0 + threadIdx.x;
    Whi[off] = __ushort_as_half((unsigned short)h);
    Wlo[off] = __ushort_as_half((unsigned short)l);
}

// ---------------------------------------------------------------------------
// fp16 3-split GEMM via mma.sync + fused bias/tanh-jet epilogue.
// BM=64, BN=128, BK=32, 256 thr (8 warps, 2x4 grid of 32x32 warp tiles),
// 3-stage cp.async pipeline, 2 CTAs/SM (decoupled barrier domains).
// MODE 1: jet(A @ W1 + b1) -> g_A2hi/lo ; MODE 2: -> g_S / g_Yb.
// ---------------------------------------------------------------------------
template<int MODE>
__global__ __launch_bounds__(256, 2)
void k_mma(const float* __restrict__ bias)
{
    const __half* __restrict__ Ahi = (MODE == 1) ? g_Ahi : g_A2hi;
    const __half* __restrict__ Alo = (MODE == 1) ? g_Alo : g_A2lo;
    const __half* __restrict__ Whi = (MODE == 1) ? g_W1hi : g_W2hi;
    const __half* __restrict__ Wlo = (MODE == 1) ? g_W1lo : g_W2lo;

    extern __shared__ char smem[];
    const uint32_t sbase = smem_u32(smem);

    const int tid  = threadIdx.x;
    const int lane = tid & 31;
    const int wid  = tid >> 5;        // 0..7
    const int wm   = wid >> 2;        // 0..1 : rows wm*32
    const int wn   = wid & 3;         // 0..3 : cols wn*32
    const int row0 = blockIdx.y * 64;
    const int col0 = blockIdx.x * 128;

    // ldmatrix lane offsets (in halves)
    const int grp = lane >> 3, idx = lane & 7;
    const int aoff = ((grp & 1) * 8 + idx) * SROW + (grp >> 1) * 8;
    const int boff = ((grp >> 1) * 8 + idx) * SROW + (grp & 1) * 8;

    float acc[2][4][4];
    #pragma unroll
    for (int mt = 0; mt < 2; mt++)
        #pragma unroll
        for (int nt = 0; nt < 4; nt++)
            #pragma unroll
            for (int q = 0; q < 4; q++) acc[mt][nt][q] = 0.0f;

    // prefetch: A 1x16B/thread per array, B 2x16B/thread per array
    const int ar = tid >> 2;            // 0..63
    const int ac = (tid & 3) * 8;       // 0,8,16,24 halves
    const int br = tid >> 1;            // 0..127
    const int bc = (tid & 1) * 16;      // 0 or 16 halves
    auto prefetch = [&](int c) {
        uint32_t st = sbase + (uint32_t)(c % NSTAGE) * STAGE;
        size_t ga = (size_t)(row0 + ar) * HID + c * 32 + ac;
        size_t gb = (size_t)(col0 + br) * HID + c * 32 + bc;
        uint32_t oa = (uint32_t)(ar * SROW + ac) * 2;
        uint32_t ob = (uint32_t)(br * SROW + bc) * 2;
        cp16(st + SM_AHI + oa, Ahi + ga);
        cp16(st + SM_ALO + oa, Alo + ga);
        cp16(st + SM_BHI + ob,      Whi + gb);
        cp16(st + SM_BHI + ob + 16, Whi + gb + 8);
        cp16(st + SM_BLO + ob,      Wlo + gb);
        cp16(st + SM_BLO + ob + 16, Wlo + gb + 8);
        asm volatile("cp.async.commit_group;" ::: "memory");
    };

    prefetch(0);
    prefetch(1);

    uint32_t fa_hi[2][2][4], fa_lo[2][2][4], fb_hi[2][2][4], fb_lo[2][2][4];

    for (int c = 0; c < NCH; c++) {
        if (c == NCH - 1) asm volatile("cp.async.wait_group 0;" ::: "memory");
        else              asm volatile("cp.async.wait_group 1;" ::: "memory");
        __syncthreads();
        // After this barrier every warp has finished its ldmatrix reads of
        // chunk c-1 (program order), so stage (c+2)%3 == (c-1)%3 is reusable.
        if (c + 2 < NCH) prefetch(c + 2);

        const uint32_t cur = sbase + (uint32_t)(c % NSTAGE) * STAGE;
        load_frags(cur, 0, wm, wn, aoff, boff, fa_hi[0], fa_lo[0], fb_hi[0], fb_lo[0]);
        load_frags(cur, 1, wm, wn, aoff, boff, fa_hi[1], fa_lo[1], fb_hi[1], fb_lo[1]);
        do_mmas(acc, fa_hi[0], fa_lo[0], fb_hi[0], fb_lo[0]);
        do_mmas(acc, fa_hi[1], fa_lo[1], fb_hi[1], fb_lo[1]);
        // no trailing __syncthreads needed (see comment above)
    }

    // ---- epilogue: bias + tanh-jet ----
    float bb[4][2];
    #pragma unroll
    for (int nt = 0; nt < 4; nt++)
        #pragma unroll
        for (int j = 0; j < 2; j++)
            bb[nt][j] = __ldg(&bias[col0 + wn*32 + nt*8 + (lane & 3)*2 + j]);

    const int role = (lane >> 2) & 3;
    const int srcL = (lane & ~15) | (lane & 3);

    if (blockIdx.y < INT_TILES) {
        #pragma unroll
        for (int mt = 0; mt < 2; mt++)
            #pragma unroll
            for (int h = 0; h < 2; h++) {
                const int grow = row0 + wm*32 + mt*16 + (lane >> 2) + 8*h;
                #pragma unroll
                for (int nt = 0; nt < 4; nt++) {
                    float o[2];
                    #pragma unroll
                    for (int j = 0; j < 2; j++) {
                        float x  = acc[mt][nt][h*2 + j];
                        float v  = __shfl_sync(0xFFFFFFFFu, x, srcL);
                        float p0 = __shfl_sync(0xFFFFFFFFu, x, srcL + 4);
                        float p1 = __shfl_sync(0xFFFFFFFFu, x, srcL + 8);
                        float y  = tanhf(v + bb[nt][j]);
                        float s  = 1.0f - y*y;
                        float r;
                        if      (role == 0) r = y;
                        else if (role == 1) r = s * p0;
                        else if (role == 2) r = s * p1;
                        else                r = fmaf(s, x, -2.0f * y * s * (p0*p0 + p1*p1));
                        o[j] = r;
                    }
                    const int colb = col0 + wn*32 + nt*8 + (lane & 3)*2;
                    if (MODE == 1) {
                        uint32_t h0, l0, h1, l1;
                        hsplit(o[0], h0, l0);
                        hsplit(o[1], h1, l1);
                        size_t off = (size_t)grow * HID + colb;
                        *(uint32_t*)&g_A2hi[off] = h0 | (h1 << 16);
                        *(uint32_t*)&g_A2lo[off] = l0 | (l1 << 16);
                    } else if (role == 3) {
                        *(float2*)&g_S[(size_t)(grow >> 2) * HID + colb] = make_float2(o[0], o[1]);
                    }
                }
            }
    } else {
        #pragma unroll
        for (int mt = 0; mt < 2; mt++)
            #pragma unroll
            for (int h = 0; h < 2; h++) {
                const int grow = row0 + wm*32 + mt*16 + (lane >> 2) + 8*h;
                if (grow < M_ROWS) {
                    #pragma unroll
                    for (int nt = 0; nt < 4; nt++) {
                        float o0 = tanhf(acc[mt][nt][h*2 + 0] + bb[nt][0]);
                        float o1 = tanhf(acc[mt][nt][h*2 + 1] + bb[nt][1]);
                        const int colb = col0 + wn*32 + nt*8 + (lane & 3)*2;
                        if (MODE == 1) {
                            uint32_t h0, l0, h1, l1;
                            hsplit(o0, h0, l0);
                            hsplit(o1, h1, l1);
                            size_t off = (size_t)grow * HID + colb;
                            *(uint32_t*)&g_A2hi[off] = h0 | (h1 << 16);
                            *(uint32_t*)&g_A2lo[off] = l0 | (l1 << 16);
                        } else {
                            *(float2*)&g_Yb[(size_t)(grow - BROW) * HID + colb] = make_float2(o0, o1);
                        }
                    }
                }
            }
    }
}

// ---------------------------------------------------------------------------
// Final reductions (unchanged, proven).
// ---------------------------------------------------------------------------
__global__ void k_final_interior(const float* __restrict__ xi, const float* __restrict__ W3)
{
    int warp = threadIdx.x >> 5;
    int lane = threadIdx.x & 31;
    int p = blockIdx.x * 8 + warp;

    float val = 0.0f;
    if (p < N_INT) {
        const float* row = &g_S[(size_t)p * HID];
        float acc = 0.0f;
        #pragma unroll 4
        for (int j = lane; j < HID; j += 32) acc = fmaf(row[j], W3[j], acc);
        #pragma unroll
        for (int o = 16; o; o >>= 1) acc += __shfl_xor_sync(0xFFFFFFFFu, acc, o);
        if (lane == 0) {
            const float PI = 3.14159265358979323846f;
            float xx = xi[2*p], yy = xi[2*p+1];
            float sy2 = sinf(PI*yy*yy), cy2 = cosf(PI*yy*yy), sx = sinf(PI*xx);
            float f = -PI*PI*(1.0f + 4.0f*yy*yy)*sx*sy2 + 2.0f*PI*sx*cy2;
            float r = acc - f;
            val = r * r;
        }
    }
    __shared__ float sh[8];
    if (lane == 0) sh[warp] = val;
    __syncthreads();
    if (threadIdx.x == 0) {
        float s = 0.0f;
        #pragma unroll
        for (int i = 0; i < 8; i++) s += sh[i];
        g_partial_i[blockIdx.x] = s;
    }
}

__global__ void k_final_boundary(const float* __restrict__ W3, const float* __restrict__ b3)
{
    int warp = threadIdx.x >> 5;
    int lane = threadIdx.x & 31;
    int p = blockIdx.x * 8 + warp;

    float val = 0.0f;
    if (p < N_B) {
        const float* row = &g_Yb[(size_t)p * HID];
        float acc = 0.0f;
        #pragma unroll 4
        for (int j = lane; j < HID; j += 32) acc = fmaf(row[j], W3[j], acc);
        #pragma unroll
        for (int o = 16; o; o >>= 1) acc += __shfl_xor_sync(0xFFFFFFFFu, acc, o);
        if (lane == 0) {
            float u = acc + b3[0];
            val = u * u;
        }
    }
    __shared__ float sh[8];
    if (lane == 0) sh[warp] = val;
    __syncthreads();
    if (threadIdx.x == 0) {
        float s = 0.0f;
        #pragma unroll
        for (int i = 0; i < 8; i++) s += sh[i];
        g_partial_b[blockIdx.x] = s;
    }
}

__global__ void k_combine(float* __restrict__ out)
{
    __shared__ float sh[256];
    int t = threadIdx.x;

    float si = 0.0f;
    for (int i = t; i < 2500; i += 256) si += g_partial_i[i];
    sh[t] = si;
    __syncthreads();
    for (int o = 128; o; o >>= 1) { if (t < o) sh[t] += sh[t + o]; __syncthreads(); }
    float interior_sum = sh[0];
    __syncthreads();

    float sb = 0.0f;
    for (int i = t; i < 100; i += 256) sb += g_partial_b[i];
    sh[t] = sb;
    __syncthreads();
    for (int o = 128; o; o >>= 1) { if (t < o) sh[t] += sh[t + o]; __syncthreads(); }

    if (t == 0) {
        float interior_loss = interior_sum / (float)N_INT;
        float boundary_loss = sh[0] / (float)N_B;
        out[0] = ALPHA * interior_loss + boundary_loss;
        out[1] = interior_loss;
        out[2] = boundary_loss;
    }
}

// ---------------------------------------------------------------------------
extern "C" void kernel_launch(void* const* d_in, const int* in_sizes, int n_in,
                              void* d_out, int out_size)
{
    const float* xi = (const float*)d_in[0];
    const float* xb = (const float*)d_in[1];
    const float* W0 = (const float*)d_in[2];
    const float* b0 = (const float*)d_in[3];
    const float* W1 = (const float*)d_in[4];
    const float* b1 = (const float*)d_in[5];
    const float* W2 = (const float*)d_in[6];
    const float* b2 = (const float*)d_in[7];
    const float* W3 = (const float*)d_in[8];
    const float* b3 = (const float*)d_in[9];

    cudaFuncSetAttribute(k_mma<1>, cudaFuncAttributeMaxDynamicSharedMemorySize, SMEM_DYN);
    cudaFuncSetAttribute(k_mma<2>, cudaFuncAttributeMaxDynamicSharedMemorySize, SMEM_DYN);

    dim3 tgrid(16, 16), tblock(32, 32);
    dim3 mma_grid(4, M_TILES);

    k_layer0<<<N_INT + N_B, 256>>>(xi, xb, W0, b0);
    k_transpose<1><<<tgrid, tblock>>>(W1);
    k_transpose<2><<<tgrid, tblock>>>(W2);
    k_mma<1><<<mma_grid, 256, SMEM_DYN>>>(b1);
    k_mma<2><<<mma_grid, 256, SMEM_DYN>>>(b2);
    k_final_interior<<<(N_INT + 7) / 8, 256>>>(xi, W3);
    k_final_boundary<<<(N_B + 7) / 8, 256>>>(W3, b3);
    k_combine<<<1, 256>>>((float*)d_out);
}